// round 5
// baseline (speedup 1.0000x reference)
#include <cuda_runtime.h>
#include <cstdint>
#include <math.h>

#define T_     256
#define B_     32
#define VOCAB_ 32000
#define EMB_   512
#define HID_   1024
#define G_     4096   // 4*HID
#define TB_    8192   // T_*B_
#define NBLK   128    // persistent blocks (1 per SM)
#define UPB    8      // hidden units per block (128*8 = 1024)
#define BH     (B_ * HID_)
#define NW     8      // warps per block in lstm_persist
#define FPAD   32     // flag padding (32 u32 = 128 B)

// chunking for the recurrence h staging
#define CHK    32                   // K per chunk
#define CSTRIDE 36                  // floats per row in chunk buf (pad 4)
#define CBYTES (32 * CSTRIDE * 4)   // 4608 B per chunk buffer

// ---------------- scratch (device globals; no allocations allowed) ----------
__device__ float g_X0[TB_ * EMB_];
__device__ float g_HA[TB_ * HID_];
__device__ float g_HB[TB_ * HID_];
__device__ float g_Xg[(size_t)TB_ * G_];
__device__ float g_h[2 * BH];              // ping-pong h state
__device__ unsigned g_flags[NBLK * FPAD];  // per-block progress flags

// ---------------- helpers ---------------------------------------------------
__device__ __forceinline__ float f2tf32(float x) {
    uint32_t u;
    asm("cvt.rna.tf32.f32 %0, %1;" : "=r"(u) : "f"(x));
    return __uint_as_float(u);
}

__device__ __forceinline__ void mma_tf32(float* d, const uint32_t* a, const uint32_t* b) {
    asm volatile(
        "mma.sync.aligned.m16n8k8.row.col.f32.tf32.tf32.f32 "
        "{%0,%1,%2,%3}, {%4,%5,%6,%7}, {%8,%9}, {%0,%1,%2,%3};\n"
        : "+f"(d[0]), "+f"(d[1]), "+f"(d[2]), "+f"(d[3])
        : "r"(a[0]), "r"(a[1]), "r"(a[2]), "r"(a[3]), "r"(b[0]), "r"(b[1]));
}

__device__ __forceinline__ float sigm(float x) { return 1.f / (1.f + expf(-x)); }

__device__ __forceinline__ unsigned ld_acq(const unsigned* p) {
    unsigned v;
    asm volatile("ld.acquire.gpu.u32 %0, [%1];" : "=r"(v) : "l"(p) : "memory");
    return v;
}

__device__ __forceinline__ void st_rel(unsigned* p, unsigned v) {
    asm volatile("st.release.gpu.u32 [%0], %1;" :: "l"(p), "r"(v) : "memory");
}

__device__ __forceinline__ void cp16(uint32_t dst, const void* src) {
    asm volatile("cp.async.cg.shared.global [%0], [%1], 16;" :: "r"(dst), "l"(src));
}
#define CP_COMMIT() asm volatile("cp.async.commit_group;")
#define CP_WAIT(N)  asm volatile("cp.async.wait_group %0;" :: "n"(N))

// ---------------- embedding gather ------------------------------------------
__global__ void gather_kernel(const int* __restrict__ data,
                              const float* __restrict__ emb,
                              float* __restrict__ X0) {
    int tb = blockIdx.x;
    int idx = data[tb];
    const float4* src = reinterpret_cast<const float4*>(emb + (size_t)idx * EMB_);
    float4* dst = reinterpret_cast<float4*>(X0 + (size_t)tb * EMB_);
    dst[threadIdx.x] = src[threadIdx.x];
}

// ---------------- state zero + flag reset -----------------------------------
__global__ void zero_state(float* __restrict__ h, unsigned* __restrict__ flags) {
    int i = blockIdx.x * blockDim.x + threadIdx.x;
    if (i < 2 * BH) h[i] = 0.f;
    if (i < NBLK * FPAD) flags[i] = 0u;
}

// ---------------- generic TF32 GEMM: C = A@B + bias (validated) -------------
__global__ __launch_bounds__(256) void gemm_tf32_bias(
    const float* __restrict__ A, int lda,
    const float* __restrict__ Bm, int ldb,
    const float* __restrict__ bias,
    float* __restrict__ C, int ldc, int K)
{
    __shared__ float As[16][132];
    __shared__ float Bs[16][136];

    const int n0 = blockIdx.x * 128;
    const int m0 = blockIdx.y * 128;
    const int tid = threadIdx.x;
    const int lane = tid & 31, warp = tid >> 5;
    const int wm = (warp & 3) * 32;
    const int wn = (warp >> 2) * 64;
    const int g = lane >> 2, tig = lane & 3;

    float acc[2][8][4];
#pragma unroll
    for (int i = 0; i < 2; i++)
#pragma unroll
        for (int j = 0; j < 8; j++)
#pragma unroll
            for (int r = 0; r < 4; r++) acc[i][j][r] = 0.f;

    float4 ra[2], rb[2];

    auto ldglobal = [&](int k0) {
#pragma unroll
        for (int i = 0; i < 2; i++) {
            int c = tid + i * 256;
            int r = c >> 2, kq = (c & 3) << 2;
            ra[i] = *reinterpret_cast<const float4*>(A + (size_t)(m0 + r) * lda + (k0 + kq));
            int k = c >> 5, nq = (c & 31) << 2;
            rb[i] = *reinterpret_cast<const float4*>(Bm + (size_t)(k0 + k) * ldb + (n0 + nq));
        }
    };
    auto st_smem = [&]() {
#pragma unroll
        for (int i = 0; i < 2; i++) {
            int c = tid + i * 256;
            int r = c >> 2, kq = (c & 3) << 2;
            As[kq + 0][r] = f2tf32(ra[i].x);
            As[kq + 1][r] = f2tf32(ra[i].y);
            As[kq + 2][r] = f2tf32(ra[i].z);
            As[kq + 3][r] = f2tf32(ra[i].w);
            int k = c >> 5, nq = (c & 31) << 2;
            float4 t;
            t.x = f2tf32(rb[i].x); t.y = f2tf32(rb[i].y);
            t.z = f2tf32(rb[i].z); t.w = f2tf32(rb[i].w);
            *reinterpret_cast<float4*>(&Bs[k][nq]) = t;
        }
    };
    auto compute = [&]() {
#pragma unroll
        for (int ks = 0; ks < 16; ks += 8) {
            uint32_t af[2][4];
#pragma unroll
            for (int mt = 0; mt < 2; mt++) {
                int mb = wm + mt * 16;
                af[mt][0] = __float_as_uint(As[ks + tig][mb + g]);
                af[mt][1] = __float_as_uint(As[ks + tig][mb + g + 8]);
                af[mt][2] = __float_as_uint(As[ks + tig + 4][mb + g]);
                af[mt][3] = __float_as_uint(As[ks + tig + 4][mb + g + 8]);
            }
#pragma unroll
            for (int nt = 0; nt < 8; nt++) {
                uint32_t bf[2];
                int nb = wn + nt * 8;
                bf[0] = __float_as_uint(Bs[ks + tig][nb + g]);
                bf[1] = __float_as_uint(Bs[ks + tig + 4][nb + g]);
                mma_tf32(acc[0][nt], af[0], bf);
                mma_tf32(acc[1][nt], af[1], bf);
            }
        }
    };

    ldglobal(0); st_smem(); __syncthreads();
    const int nk = K >> 4;
    for (int kb = 0; kb < nk; kb++) {
        bool more = (kb + 1 < nk);
        if (more) ldglobal((kb + 1) << 4);
        compute();
        __syncthreads();
        if (more) { st_smem(); __syncthreads(); }
    }

#pragma unroll
    for (int mt = 0; mt < 2; mt++) {
        int m = m0 + wm + mt * 16 + g;
#pragma unroll
        for (int nt = 0; nt < 8; nt++) {
            int n = n0 + wn + nt * 8 + 2 * tig;
            float bx = bias[n], by = bias[n + 1];
            float2 v0 = make_float2(acc[mt][nt][0] + bx, acc[mt][nt][1] + by);
            float2 v1 = make_float2(acc[mt][nt][2] + bx, acc[mt][nt][3] + by);
            *reinterpret_cast<float2*>(C + (size_t)m * ldc + n) = v0;
            *reinterpret_cast<float2*>(C + (size_t)(m + 8) * ldc + n) = v1;
        }
    }
}

// ---------------- persistent LSTM layer -------------------------------------
// 128 blocks x 256 threads (8 warps). Block owns UPB=8 units (32 gate cols).
// Wh slice resident in SMEM as mma B-fragments for all 256 steps.
// K split 8 ways across warps; warp w's K range [128w,128w+128) is produced by
// blocks 16w..16w+15 only -> fine-grained per-warp flag wait, NO global barrier.
// c state in registers; Xg prefetched; h rounded to tf32 at store.
//
// Dynamic SMEM:
//   Whs : float2[128 ko][4 nt][32 lane]              = 131072 B
//   Hb  : per-warp 2 x [32 m][36] chunk buffers      =  73728 B
//   scr : aliases Hb (32 KB needed; protected by the post-store syncthreads)
#define WHS_BYTES 131072
#define HB_BYTES  (NW * 2 * CBYTES)
#define SMEM_PERSIST (WHS_BYTES + HB_BYTES)

__global__ __launch_bounds__(256, 1) void lstm_persist(
    const float* __restrict__ Xg,
    const float* __restrict__ Wh,      // [HID_][G_] (rows Din..Din+H of W)
    float* __restrict__ hbuf,          // [2][BH] (zeroed; tf32-rounded values)
    float* __restrict__ Hout,          // [TB_][HID_]
    unsigned* __restrict__ flags)      // [NBLK*FPAD] (zeroed)
{
    extern __shared__ char smx[];
    float2* Whs = reinterpret_cast<float2*>(smx);
    float*  scr = reinterpret_cast<float*>(smx + WHS_BYTES);   // alias of Hb

    const int tid = threadIdx.x;
    const int lane = tid & 31, warp = tid >> 5;
    const int g = lane >> 2, tig = lane & 3;
    const int u0 = blockIdx.x * UPB;

    const uint32_t smem_u32 = (uint32_t)__cvta_generic_to_shared(smx);
    const uint32_t hb_u32 = smem_u32 + WHS_BYTES + warp * 2 * CBYTES;
    float* hb_gen = reinterpret_cast<float*>(smx + WHS_BYTES + warp * 2 * CBYTES);

    // ---- one-time: load Wh slice into fragment layout ----
    for (int ko = warp; ko < 128; ko += NW) {
#pragma unroll
        for (int nt = 0; nt < 4; nt++) {
            int col = nt * HID_ + u0 + g;
            float b0 = Wh[(size_t)(ko * 8 + tig) * G_ + col];
            float b1 = Wh[(size_t)(ko * 8 + tig + 4) * G_ + col];
            Whs[(ko * 4 + nt) * 32 + lane] = make_float2(f2tf32(b0), f2tf32(b1));
        }
    }
    __syncthreads();

    // pointwise mapping for this thread: p = tid -> (batch m, unit ul)
    const int pm = tid >> 3, pul = tid & 7;
    const int pmt = pm >> 4;
    const int pgg = (pm & 15) & 7, phi = (pm & 15) >> 3;
    const int pr = phi * 2 + (pul & 1);
    const int pln = pgg * 4 + (pul >> 1);
    const size_t xgbase = (size_t)pm * G_ + u0 + pul;

    // cp.async addressing for this thread
    const int r8 = lane >> 3, kk = lane & 7;
    const int kw = warp * 128;         // this warp's K base

    // producer flag this lane watches (lanes 0..15): blocks 16*warp .. +15
    const unsigned* myflag = &flags[(warp * 16 + (lane & 15)) * FPAD];

    float creg = 0.f;
    float xr[4];
#pragma unroll
    for (int s = 0; s < 4; s++) xr[s] = Xg[xgbase + s * HID_];   // t = 0 prefetch

    for (int t = 0; t < T_; t++) {
        const float* hin = hbuf + (t & 1) * BH;
        float* hnx = hbuf + ((t + 1) & 1) * BH;

        // ---- fine-grained producer wait: this warp's 16 source blocks ----
        if (t > 0) {
            if (lane < 16) {
                while (ld_acq(myflag) < (unsigned)t) { }
            }
            __syncwarp();
        }

        float acc[2][4][4];
#pragma unroll
        for (int mt = 0; mt < 2; mt++)
#pragma unroll
            for (int nt = 0; nt < 4; nt++)
#pragma unroll
                for (int r = 0; r < 4; r++) acc[mt][nt][r] = 0.f;

        auto cp_chunk = [&](int c, int b) {
            const int kbase = kw + c * CHK;
            const uint32_t dbase = hb_u32 + b * CBYTES + (kk * 4) * 4;
            const float* sbase = hin + r8 * HID_ + kbase + kk * 4;
#pragma unroll
            for (int p = 0; p < 8; p++) {
                int row4 = p * 4;
                cp16(dbase + (uint32_t)((row4 + r8) * CSTRIDE) * 4,
                     sbase + (size_t)row4 * HID_);
            }
            CP_COMMIT();
        };
        auto compute_chunk = [&](int c, int b) {
            const float* buf = hb_gen + b * (CBYTES / 4);
#pragma unroll
            for (int k8 = 0; k8 < 4; k8++) {
                int ko = warp * 16 + c * 4 + k8;
                int kA = k8 * 8 + tig;
                uint32_t af[2][4];
#pragma unroll
                for (int mt = 0; mt < 2; mt++) {
                    int mb = mt * 16;
                    af[mt][0] = __float_as_uint(buf[(mb + g) * CSTRIDE + kA]);
                    af[mt][1] = __float_as_uint(buf[(mb + g + 8) * CSTRIDE + kA]);
                    af[mt][2] = __float_as_uint(buf[(mb + g) * CSTRIDE + kA + 4]);
                    af[mt][3] = __float_as_uint(buf[(mb + g + 8) * CSTRIDE + kA + 4]);
                }
#pragma unroll
                for (int nt = 0; nt < 4; nt++) {
                    float2 bb = Whs[(ko * 4 + nt) * 32 + lane];
                    uint32_t bf[2] = {__float_as_uint(bb.x), __float_as_uint(bb.y)};
                    mma_tf32(acc[0][nt], af[0], bf);
                    mma_tf32(acc[1][nt], af[1], bf);
                }
            }
        };

        // 2-deep cp.async pipeline over 4 chunks
        cp_chunk(0, 0);
        cp_chunk(1, 1);
        CP_WAIT(1); __syncwarp();
        compute_chunk(0, 0);
        cp_chunk(2, 0);
        CP_WAIT(1); __syncwarp();
        compute_chunk(1, 1);
        cp_chunk(3, 1);
        CP_WAIT(1); __syncwarp();
        compute_chunk(2, 0);
        CP_WAIT(0); __syncwarp();
        compute_chunk(3, 1);

        // ---- reduce K-partials across 8 warps (scr aliases chunk bufs) ----
        __syncthreads();
#pragma unroll
        for (int mt = 0; mt < 2; mt++)
#pragma unroll
            for (int nt = 0; nt < 4; nt++)
#pragma unroll
                for (int r = 0; r < 4; r++) {
                    int ridx = mt * 16 + nt * 4 + r;
                    scr[((warp * 32 + ridx) << 5) + lane] = acc[mt][nt][r];
                }
        __syncthreads();

        // ---- pointwise: one (batch, unit) pair per thread ----
        float hh;
        {
            float gv[4];
#pragma unroll
            for (int s = 0; s < 4; s++) {
                int ridx = pmt * 16 + s * 4 + pr;
                float v = 0.f;
#pragma unroll
                for (int w = 0; w < NW; w++)
                    v += scr[((w * 32 + ridx) << 5) + pln];
                gv[s] = v + xr[s];
            }
            float cc = creg;
            cc = sigm(gv[2] + 1.f) * cc + sigm(gv[0]) * tanhf(gv[1]);
            hh = sigm(gv[3]) * tanhf(cc);
            creg = cc;
            hnx[pm * HID_ + u0 + pul] = f2tf32(hh);   // rounded once for next-step mma
        }

        // ---- publish progress; overlap Hout store + Xg prefetch ----
        __syncthreads();               // h stores issued + protects scr alias
        if (t < T_ - 1) {
            if (tid == 0) {
                __threadfence();
                st_rel(&flags[blockIdx.x * FPAD], (unsigned)(t + 1));
            }
            Hout[((size_t)(t * B_ + pm)) * HID_ + u0 + pul] = hh;
            const size_t xb = xgbase + (size_t)(t + 1) * B_ * G_;
#pragma unroll
            for (int s = 0; s < 4; s++) xr[s] = Xg[xb + s * HID_];
        } else {
            Hout[((size_t)(t * B_ + pm)) * HID_ + u0 + pul] = hh;
        }
    }
}

// ---------------- launch ----------------------------------------------------
extern "C" void kernel_launch(void* const* d_in, const int* in_sizes, int n_in,
                              void* d_out, int out_size) {
    const int*   data = (const int*)d_in[0];
    const float* emb  = (const float*)d_in[2];
    const float* W0   = (const float*)d_in[3];
    const float* b0   = (const float*)d_in[4];
    const float* W1   = (const float*)d_in[5];
    const float* b1   = (const float*)d_in[6];
    const float* W2   = (const float*)d_in[7];
    const float* b2   = (const float*)d_in[8];
    const float* Wd   = (const float*)d_in[9];
    const float* bd   = (const float*)d_in[10];
    float* out = (float*)d_out;
    (void)in_sizes; (void)n_in; (void)out_size;

    float *X0, *HA, *HB, *Xg, *h;
    unsigned* flags;
    cudaGetSymbolAddress((void**)&X0, g_X0);
    cudaGetSymbolAddress((void**)&HA, g_HA);
    cudaGetSymbolAddress((void**)&HB, g_HB);
    cudaGetSymbolAddress((void**)&Xg, g_Xg);
    cudaGetSymbolAddress((void**)&h,  g_h);
    cudaGetSymbolAddress((void**)&flags, g_flags);

    cudaFuncSetAttribute(lstm_persist, cudaFuncAttributeMaxDynamicSharedMemorySize,
                         SMEM_PERSIST);

    gather_kernel<<<TB_, 128>>>(data, emb, X0);

    const int zgrid = (2 * BH + 255) / 256;

    // layer 0
    zero_state<<<zgrid, 256>>>(h, flags);
    gemm_tf32_bias<<<dim3(G_ / 128, TB_ / 128), 256>>>(X0, EMB_, W0, G_, b0, Xg, G_, EMB_);
    lstm_persist<<<NBLK, 256, SMEM_PERSIST>>>(Xg, W0 + (size_t)EMB_ * G_, h, HA, flags);

    // layer 1
    zero_state<<<zgrid, 256>>>(h, flags);
    gemm_tf32_bias<<<dim3(G_ / 128, TB_ / 128), 256>>>(HA, HID_, W1, G_, b1, Xg, G_, HID_);
    lstm_persist<<<NBLK, 256, SMEM_PERSIST>>>(Xg, W1 + (size_t)HID_ * G_, h, HB, flags);

    // layer 2
    zero_state<<<zgrid, 256>>>(h, flags);
    gemm_tf32_bias<<<dim3(G_ / 128, TB_ / 128), 256>>>(HB, HID_, W2, G_, b2, Xg, G_, HID_);
    lstm_persist<<<NBLK, 256, SMEM_PERSIST>>>(Xg, W2 + (size_t)HID_ * G_, h, HA, flags);

    // projection
    gemm_tf32_bias<<<dim3(VOCAB_ / 128, TB_ / 128), 256>>>(HA, HID_, Wd, VOCAB_, bd,
                                                           out, VOCAB_, HID_);
}

// round 6
// speedup vs baseline: 1.2151x; 1.2151x over previous
#include <cuda_runtime.h>
#include <cstdint>
#include <math.h>

#define T_     256
#define B_     32
#define VOCAB_ 32000
#define EMB_   512
#define HID_   1024
#define G_     4096   // 4*HID
#define TB_    8192   // T_*B_
#define NBLK   128    // persistent blocks (1 per SM)
#define UPB    8      // hidden units per block (128*8 = 1024)
#define BH     (B_ * HID_)
#define NW     8      // warps per block in lstm_persist

// persistent-kernel chunking
#define CHK    32
#define CSTRIDE 36
#define CBYTES (32 * CSTRIDE * 4)

// pipelined GEMM config
#define GBM 128
#define GBN 256
#define GBK 16
#define ASTRIDE 20                    // A smem row stride (floats)
#define BSTRIDE 264                   // B smem k-row stride (floats)
#define A_STAGE (GBM * ASTRIDE)       // 2560 floats
#define B_STAGE (GBK * BSTRIDE)       // 4224 floats
#define STAGE_FLOATS (A_STAGE + B_STAGE)
#define GEMM_SMEM (3 * STAGE_FLOATS * 4)   // 81408 B
#define GSW 8                          // supertile width (N tiles)

// ---------------- scratch (device globals; no allocations allowed) ----------
__device__ float g_X0[TB_ * EMB_];
__device__ float g_HA[TB_ * HID_];
__device__ float g_HB[TB_ * HID_];
__device__ float g_Xg[(size_t)TB_ * G_];   // also reused for rounded Wd
__device__ float g_Wr[HID_ * G_];          // rounded pre-gate weights (16.8 MB)
__device__ float g_h[2 * BH];
__device__ unsigned g_bar;

// ---------------- helpers ---------------------------------------------------
__device__ __forceinline__ float f2tf32(float x) {
    uint32_t u;
    asm("cvt.rna.tf32.f32 %0, %1;" : "=r"(u) : "f"(x));
    return __uint_as_float(u);
}

__device__ __forceinline__ void mma_tf32(float* d, const uint32_t* a, const uint32_t* b) {
    asm volatile(
        "mma.sync.aligned.m16n8k8.row.col.f32.tf32.tf32.f32 "
        "{%0,%1,%2,%3}, {%4,%5,%6,%7}, {%8,%9}, {%0,%1,%2,%3};\n"
        : "+f"(d[0]), "+f"(d[1]), "+f"(d[2]), "+f"(d[3])
        : "r"(a[0]), "r"(a[1]), "r"(a[2]), "r"(a[3]), "r"(b[0]), "r"(b[1]));
}

__device__ __forceinline__ float sigm(float x) { return 1.f / (1.f + expf(-x)); }

__device__ __forceinline__ unsigned ld_acq(const unsigned* p) {
    unsigned v;
    asm volatile("ld.acquire.gpu.u32 %0, [%1];" : "=r"(v) : "l"(p) : "memory");
    return v;
}

__device__ __forceinline__ void cp16(uint32_t dst, const void* src) {
    asm volatile("cp.async.cg.shared.global [%0], [%1], 16;" :: "r"(dst), "l"(src));
}
#define CP_COMMIT() asm volatile("cp.async.commit_group;")
#define CP_WAIT(N)  asm volatile("cp.async.wait_group %0;" :: "n"(N))

// ---------------- embedding gather (tf32-rounded) ---------------------------
__global__ void gather_kernel(const int* __restrict__ data,
                              const float* __restrict__ emb,
                              float* __restrict__ X0) {
    int tb = blockIdx.x;
    int idx = data[tb];
    const float4* src = reinterpret_cast<const float4*>(emb + (size_t)idx * EMB_);
    float4* dst = reinterpret_cast<float4*>(X0 + (size_t)tb * EMB_);
    float4 v = src[threadIdx.x];
    v.x = f2tf32(v.x); v.y = f2tf32(v.y); v.z = f2tf32(v.z); v.w = f2tf32(v.w);
    dst[threadIdx.x] = v;
}

// ---------------- tf32 round-copy (weights) ---------------------------------
__global__ void round_copy(const float* __restrict__ src, float* __restrict__ dst,
                           int n4) {
    int i = blockIdx.x * blockDim.x + threadIdx.x;
    if (i < n4) {
        float4 v = reinterpret_cast<const float4*>(src)[i];
        v.x = f2tf32(v.x); v.y = f2tf32(v.y); v.z = f2tf32(v.z); v.w = f2tf32(v.w);
        reinterpret_cast<float4*>(dst)[i] = v;
    }
}

// ---------------- state zero + barrier reset --------------------------------
__global__ void zero_state(float* __restrict__ h, unsigned* __restrict__ bar) {
    int i = blockIdx.x * blockDim.x + threadIdx.x;
    if (i < 2 * BH) h[i] = 0.f;
    if (i == 0) *bar = 0u;
}

// ---------------- pipelined TF32 GEMM: C = A@B + bias -----------------------
// A [M,lda] row-major (pre-rounded tf32), B [K,ldb] row-major (pre-rounded).
// 128x256 tiles, 512 threads, 3-stage cp.async pipeline, supertile swizzle.
__global__ __launch_bounds__(512, 1) void gemm_tf32_pipe(
    const float* __restrict__ A, int lda,
    const float* __restrict__ Bm, int ldb,
    const float* __restrict__ bias,
    float* __restrict__ C, int ldc, int K, int ntiles, int mtiles)
{
    extern __shared__ float sm[];

    // supertile swizzle: consecutive blocks share an L2-resident A/B slab
    int lin = blockIdx.x;
    int n_t, m_t;
    {
        int full = ntiles / GSW;
        int blocksFull = full * GSW * mtiles;
        if (lin < blocksFull) {
            int sid = lin / (GSW * mtiles);
            int r = lin - sid * (GSW * mtiles);
            n_t = sid * GSW + (r % GSW);
            m_t = r / GSW;
        } else {
            int r = lin - blocksFull;
            int wd = ntiles - full * GSW;
            n_t = full * GSW + (r % wd);
            m_t = r / wd;
        }
    }
    const int n0 = n_t * GBN;
    const int m0 = m_t * GBM;

    const int tid = threadIdx.x;
    const int lane = tid & 31, warp = tid >> 5;
    const int wm = (warp & 3) * 32;
    const int wn = (warp >> 2) * 64;
    const int g = lane >> 2, tig = lane & 3;

    const uint32_t sm_u32 = (uint32_t)__cvta_generic_to_shared(sm);

    float acc[2][8][4];
#pragma unroll
    for (int i = 0; i < 2; i++)
#pragma unroll
        for (int j = 0; j < 8; j++)
#pragma unroll
            for (int r = 0; r < 4; r++) acc[i][j][r] = 0.f;

    const int am = tid >> 2, akq = (tid & 3) << 2;

    auto issue_stage = [&](int kb, int s) {
        int k0 = kb * GBK;
        uint32_t aS = sm_u32 + (uint32_t)(s * STAGE_FLOATS) * 4;
        uint32_t bS = aS + A_STAGE * 4;
        cp16(aS + (uint32_t)(am * ASTRIDE + akq) * 4,
             A + (size_t)(m0 + am) * lda + k0 + akq);
#pragma unroll
        for (int i = 0; i < 2; i++) {
            int idx = tid + i * 512;
            int k = idx >> 6, nq = (idx & 63) << 2;
            cp16(bS + (uint32_t)(k * BSTRIDE + nq) * 4,
                 Bm + (size_t)(k0 + k) * ldb + n0 + nq);
        }
        CP_COMMIT();
    };
    auto compute_stage = [&](int s) {
        const float* aS = sm + s * STAGE_FLOATS;
        const float* bS = aS + A_STAGE;
#pragma unroll
        for (int ks = 0; ks < GBK; ks += 8) {
            uint32_t af[2][4];
#pragma unroll
            for (int mt = 0; mt < 2; mt++) {
                int mb = wm + mt * 16 + g;
                af[mt][0] = __float_as_uint(aS[mb * ASTRIDE + ks + tig]);
                af[mt][1] = __float_as_uint(aS[(mb + 8) * ASTRIDE + ks + tig]);
                af[mt][2] = __float_as_uint(aS[mb * ASTRIDE + ks + tig + 4]);
                af[mt][3] = __float_as_uint(aS[(mb + 8) * ASTRIDE + ks + tig + 4]);
            }
#pragma unroll
            for (int nt = 0; nt < 8; nt++) {
                int nb = wn + nt * 8 + g;
                uint32_t bf[2];
                bf[0] = __float_as_uint(bS[(ks + tig) * BSTRIDE + nb]);
                bf[1] = __float_as_uint(bS[(ks + tig + 4) * BSTRIDE + nb]);
                mma_tf32(acc[0][nt], af[0], bf);
                mma_tf32(acc[1][nt], af[1], bf);
            }
        }
    };

    const int nk = K >> 4;
    issue_stage(0, 0);
    issue_stage(1, 1);
    int s = 0;
    for (int kb = 0; kb < nk; kb++) {
        if (kb < nk - 1) { CP_WAIT(1); } else { CP_WAIT(0); }
        __syncthreads();
        compute_stage(s);
        if (kb + 2 < nk) {
            int nb = s + 2; if (nb >= 3) nb -= 3;
            issue_stage(kb + 2, nb);
        }
        s = s + 1; if (s == 3) s = 0;
    }

#pragma unroll
    for (int mt = 0; mt < 2; mt++) {
        int m = m0 + wm + mt * 16 + g;
#pragma unroll
        for (int nt = 0; nt < 8; nt++) {
            int n = n0 + wn + nt * 8 + 2 * tig;
            float bx = bias[n], by = bias[n + 1];
            float2 v0 = make_float2(acc[mt][nt][0] + bx, acc[mt][nt][1] + by);
            float2 v1 = make_float2(acc[mt][nt][2] + bx, acc[mt][nt][3] + by);
            *reinterpret_cast<float2*>(C + (size_t)m * ldc + n) = v0;
            *reinterpret_cast<float2*>(C + (size_t)(m + 8) * ldc + n) = v1;
        }
    }
}

// ---------------- persistent LSTM layer (R4 config: central barrier) --------
#define WHS_BYTES 131072
#define HB_BYTES  (NW * 2 * CBYTES)
#define SMEM_PERSIST (WHS_BYTES + HB_BYTES)

__global__ __launch_bounds__(256, 1) void lstm_persist(
    const float* __restrict__ Xg,
    const float* __restrict__ Wh,
    float* __restrict__ hbuf,
    float* __restrict__ Hout,
    unsigned* __restrict__ bar)
{
    extern __shared__ char smx[];
    float2* Whs = reinterpret_cast<float2*>(smx);
    float*  scr = reinterpret_cast<float*>(smx + WHS_BYTES);

    const int tid = threadIdx.x;
    const int lane = tid & 31, warp = tid >> 5;
    const int g = lane >> 2, tig = lane & 3;
    const int u0 = blockIdx.x * UPB;

    const uint32_t smem_u32 = (uint32_t)__cvta_generic_to_shared(smx);
    const uint32_t hb_u32 = smem_u32 + WHS_BYTES + warp * 2 * CBYTES;
    float* hb_gen = reinterpret_cast<float*>(smx + WHS_BYTES + warp * 2 * CBYTES);

    for (int ko = warp; ko < 128; ko += NW) {
#pragma unroll
        for (int nt = 0; nt < 4; nt++) {
            int col = nt * HID_ + u0 + g;
            float b0 = Wh[(size_t)(ko * 8 + tig) * G_ + col];
            float b1 = Wh[(size_t)(ko * 8 + tig + 4) * G_ + col];
            Whs[(ko * 4 + nt) * 32 + lane] = make_float2(f2tf32(b0), f2tf32(b1));
        }
    }
    __syncthreads();

    const int pm = tid >> 3, pul = tid & 7;
    const int pmt = pm >> 4;
    const int pgg = (pm & 15) & 7, phi = (pm & 15) >> 3;
    const int pr = phi * 2 + (pul & 1);
    const int pln = pgg * 4 + (pul >> 1);
    const size_t xgbase = (size_t)pm * G_ + u0 + pul;

    const int r8 = lane >> 3, kk = lane & 7;
    const int kw = warp * 128;

    float creg = 0.f;
    float xr[4];
#pragma unroll
    for (int s = 0; s < 4; s++) xr[s] = Xg[xgbase + s * HID_];

    for (int t = 0; t < T_; t++) {
        const float* hin = hbuf + (t & 1) * BH;
        float* hnx = hbuf + ((t + 1) & 1) * BH;

        float acc[2][4][4];
#pragma unroll
        for (int mt = 0; mt < 2; mt++)
#pragma unroll
            for (int nt = 0; nt < 4; nt++)
#pragma unroll
                for (int r = 0; r < 4; r++) acc[mt][nt][r] = 0.f;

        auto cp_chunk = [&](int c, int b) {
            const int kbase = kw + c * CHK;
            const uint32_t dbase = hb_u32 + b * CBYTES + (kk * 4) * 4;
            const float* sbase = hin + r8 * HID_ + kbase + kk * 4;
#pragma unroll
            for (int p = 0; p < 8; p++) {
                int row4 = p * 4;
                cp16(dbase + (uint32_t)((row4 + r8) * CSTRIDE) * 4,
                     sbase + (size_t)row4 * HID_);
            }
            CP_COMMIT();
        };
        auto compute_chunk = [&](int c, int b) {
            const float* buf = hb_gen + b * (CBYTES / 4);
#pragma unroll
            for (int k8 = 0; k8 < 4; k8++) {
                int ko = warp * 16 + c * 4 + k8;
                int kA = k8 * 8 + tig;
                uint32_t af[2][4];
#pragma unroll
                for (int mt = 0; mt < 2; mt++) {
                    int mb = mt * 16;
                    af[mt][0] = __float_as_uint(buf[(mb + g) * CSTRIDE + kA]);
                    af[mt][1] = __float_as_uint(buf[(mb + g + 8) * CSTRIDE + kA]);
                    af[mt][2] = __float_as_uint(buf[(mb + g) * CSTRIDE + kA + 4]);
                    af[mt][3] = __float_as_uint(buf[(mb + g + 8) * CSTRIDE + kA + 4]);
                }
#pragma unroll
                for (int nt = 0; nt < 4; nt++) {
                    float2 bb = Whs[(ko * 4 + nt) * 32 + lane];
                    uint32_t bf[2] = {__float_as_uint(bb.x), __float_as_uint(bb.y)};
                    mma_tf32(acc[0][nt], af[0], bf);
                    mma_tf32(acc[1][nt], af[1], bf);
                }
            }
        };

        cp_chunk(0, 0);
        cp_chunk(1, 1);
        CP_WAIT(1); __syncwarp();
        compute_chunk(0, 0);
        cp_chunk(2, 0);
        CP_WAIT(1); __syncwarp();
        compute_chunk(1, 1);
        cp_chunk(3, 1);
        CP_WAIT(1); __syncwarp();
        compute_chunk(2, 0);
        CP_WAIT(0); __syncwarp();
        compute_chunk(3, 1);

        __syncthreads();
#pragma unroll
        for (int mt = 0; mt < 2; mt++)
#pragma unroll
            for (int nt = 0; nt < 4; nt++)
#pragma unroll
                for (int r = 0; r < 4; r++) {
                    int ridx = mt * 16 + nt * 4 + r;
                    scr[((warp * 32 + ridx) << 5) + lane] = acc[mt][nt][r];
                }
        __syncthreads();

        float hh;
        {
            float gv[4];
#pragma unroll
            for (int s = 0; s < 4; s++) {
                int ridx = pmt * 16 + s * 4 + pr;
                float v = 0.f;
#pragma unroll
                for (int w = 0; w < NW; w++)
                    v += scr[((w * 32 + ridx) << 5) + pln];
                gv[s] = v + xr[s];
            }
            float cc = creg;
            cc = sigm(gv[2] + 1.f) * cc + sigm(gv[0]) * tanhf(gv[1]);
            hh = sigm(gv[3]) * tanhf(cc);
            creg = cc;
            hnx[pm * HID_ + u0 + pul] = f2tf32(hh);
        }

        if (t < T_ - 1) {
            __syncthreads();
            if (tid == 0) {
                __threadfence();
                atomicAdd(bar, 1u);
            }
            Hout[((size_t)(t * B_ + pm)) * HID_ + u0 + pul] = f2tf32(hh);
            const size_t xb = xgbase + (size_t)(t + 1) * B_ * G_;
#pragma unroll
            for (int s = 0; s < 4; s++) xr[s] = Xg[xb + s * HID_];
            if (tid == 0) {
                unsigned target = (unsigned)(t + 1) * NBLK;
                while (ld_acq(bar) < target) { }
            }
            __syncthreads();
        } else {
            Hout[((size_t)(t * B_ + pm)) * HID_ + u0 + pul] = f2tf32(hh);
        }
    }
}

// ---------------- launch ----------------------------------------------------
extern "C" void kernel_launch(void* const* d_in, const int* in_sizes, int n_in,
                              void* d_out, int out_size) {
    const int*   data = (const int*)d_in[0];
    const float* emb  = (const float*)d_in[2];
    const float* W0   = (const float*)d_in[3];
    const float* b0   = (const float*)d_in[4];
    const float* W1   = (const float*)d_in[5];
    const float* b1   = (const float*)d_in[6];
    const float* W2   = (const float*)d_in[7];
    const float* b2   = (const float*)d_in[8];
    const float* Wd   = (const float*)d_in[9];
    const float* bd   = (const float*)d_in[10];
    float* out = (float*)d_out;
    (void)in_sizes; (void)n_in; (void)out_size;

    float *X0, *HA, *HB, *Xg, *Wr, *h;
    unsigned* bar;
    cudaGetSymbolAddress((void**)&X0, g_X0);
    cudaGetSymbolAddress((void**)&HA, g_HA);
    cudaGetSymbolAddress((void**)&HB, g_HB);
    cudaGetSymbolAddress((void**)&Xg, g_Xg);
    cudaGetSymbolAddress((void**)&Wr, g_Wr);
    cudaGetSymbolAddress((void**)&h,  g_h);
    cudaGetSymbolAddress((void**)&bar, g_bar);

    cudaFuncSetAttribute(lstm_persist, cudaFuncAttributeMaxDynamicSharedMemorySize,
                         SMEM_PERSIST);
    cudaFuncSetAttribute(gemm_tf32_pipe, cudaFuncAttributeMaxDynamicSharedMemorySize,
                         GEMM_SMEM);

    gather_kernel<<<TB_, 128>>>(data, emb, X0);

    const int zgrid = (2 * BH + 255) / 256;
    const int MT = TB_ / GBM;          // 64

    // layer 0 (Din = 512)
    round_copy<<<(EMB_ * G_ / 4 + 255) / 256, 256>>>(W0, Wr, EMB_ * G_ / 4);
    zero_state<<<zgrid, 256>>>(h, bar);
    gemm_tf32_pipe<<<MT * (G_ / GBN), 512, GEMM_SMEM>>>(
        X0, EMB_, Wr, G_, b0, Xg, G_, EMB_, G_ / GBN, MT);
    lstm_persist<<<NBLK, 256, SMEM_PERSIST>>>(Xg, W0 + (size_t)EMB_ * G_, h, HA, bar);

    // layer 1
    round_copy<<<(HID_ * G_ / 4 + 255) / 256, 256>>>(W1, Wr, HID_ * G_ / 4);
    zero_state<<<zgrid, 256>>>(h, bar);
    gemm_tf32_pipe<<<MT * (G_ / GBN), 512, GEMM_SMEM>>>(
        HA, HID_, Wr, G_, b1, Xg, G_, HID_, G_ / GBN, MT);
    lstm_persist<<<NBLK, 256, SMEM_PERSIST>>>(Xg, W1 + (size_t)HID_ * G_, h, HB, bar);

    // layer 2
    round_copy<<<(HID_ * G_ / 4 + 255) / 256, 256>>>(W2, Wr, HID_ * G_ / 4);
    zero_state<<<zgrid, 256>>>(h, bar);
    gemm_tf32_pipe<<<MT * (G_ / GBN), 512, GEMM_SMEM>>>(
        HB, HID_, Wr, G_, b2, Xg, G_, HID_, G_ / GBN, MT);
    lstm_persist<<<NBLK, 256, SMEM_PERSIST>>>(Xg, W2 + (size_t)HID_ * G_, h, HA, bar);

    // projection: round Wd into the now-dead Xg buffer, then GEMM
    round_copy<<<(HID_ * VOCAB_ / 4 + 255) / 256, 256>>>(Wd, Xg, HID_ * VOCAB_ / 4);
    gemm_tf32_pipe<<<MT * (VOCAB_ / GBN), 512, GEMM_SMEM>>>(
        HA, HID_, Xg, VOCAB_, bd, out, VOCAB_, HID_, VOCAB_ / GBN, MT);
}

// round 8
// speedup vs baseline: 1.2498x; 1.0286x over previous
#include <cuda_runtime.h>
#include <cstdint>
#include <math.h>

#define T_     256
#define B_     32
#define VOCAB_ 32000
#define EMB_   512
#define HID_   1024
#define G_     4096   // 4*HID
#define TB_    8192   // T_*B_
#define NBLK   128    // persistent blocks (1 per SM)
#define UPB    8      // hidden units per block (128*8 = 1024)
#define BH     (B_ * HID_)
#define NW     8      // warps per block in lstm_persist

// persistent-kernel chunking
#define CHK    32
#define CSTRIDE 36
#define CBYTES (32 * CSTRIDE * 4)

// pipelined GEMM config (K-stage = 32)
#define GBM 128
#define GBN 256
#define GBK 32
#define ASTRIDE 36                    // A smem row stride (floats)
#define BSTRIDE 264                   // B smem k-row stride (floats)
#define A_STAGE (GBM * ASTRIDE)       // 4608 floats
#define B_STAGE (GBK * BSTRIDE)       // 8448 floats
#define STAGE_FLOATS (A_STAGE + B_STAGE)
#define GEMM_SMEM (3 * STAGE_FLOATS * 4)   // 156672 B
#define GSW 8                          // supertile width (N tiles)

// ---------------- scratch (device globals; no allocations allowed) ----------
__device__ float g_X0[TB_ * EMB_];
__device__ float g_HA[TB_ * HID_];
__device__ float g_HB[TB_ * HID_];
__device__ float g_Xg[(size_t)TB_ * G_];   // also reused for rounded Wd
__device__ float g_Wr[HID_ * G_];          // rounded pre-gate weights (16.8 MB)
__device__ float g_h[2 * BH];
__device__ unsigned g_bar;

// ---------------- helpers ---------------------------------------------------
__device__ __forceinline__ float f2tf32(float x) {
    uint32_t u;
    asm("cvt.rna.tf32.f32 %0, %1;" : "=r"(u) : "f"(x));
    return __uint_as_float(u);
}

__device__ __forceinline__ void mma_tf32(float* d, const uint32_t* a, const uint32_t* b) {
    asm volatile(
        "mma.sync.aligned.m16n8k8.row.col.f32.tf32.tf32.f32 "
        "{%0,%1,%2,%3}, {%4,%5,%6,%7}, {%8,%9}, {%0,%1,%2,%3};\n"
        : "+f"(d[0]), "+f"(d[1]), "+f"(d[2]), "+f"(d[3])
        : "r"(a[0]), "r"(a[1]), "r"(a[2]), "r"(a[3]), "r"(b[0]), "r"(b[1]));
}

__device__ __forceinline__ float sigm(float x) { return 1.f / (1.f + expf(-x)); }

__device__ __forceinline__ unsigned ld_acq(const unsigned* p) {
    unsigned v;
    asm volatile("ld.acquire.gpu.u32 %0, [%1];" : "=r"(v) : "l"(p) : "memory");
    return v;
}

__device__ __forceinline__ void cp16(uint32_t dst, const void* src) {
    asm volatile("cp.async.cg.shared.global [%0], [%1], 16;" :: "r"(dst), "l"(src));
}
#define CP_COMMIT() asm volatile("cp.async.commit_group;")
#define CP_WAIT(N)  asm volatile("cp.async.wait_group %0;" :: "n"(N))

// ---------------- embedding gather (tf32-rounded) ---------------------------
__global__ void gather_kernel(const int* __restrict__ data,
                              const float* __restrict__ emb,
                              float* __restrict__ X0) {
    int tb = blockIdx.x;
    int idx = data[tb];
    const float4* src = reinterpret_cast<const float4*>(emb + (size_t)idx * EMB_);
    float4* dst = reinterpret_cast<float4*>(X0 + (size_t)tb * EMB_);
    float4 v = src[threadIdx.x];
    v.x = f2tf32(v.x); v.y = f2tf32(v.y); v.z = f2tf32(v.z); v.w = f2tf32(v.w);
    dst[threadIdx.x] = v;
}

// ---------------- tf32 round-copy (weights) ---------------------------------
__global__ void round_copy(const float* __restrict__ src, float* __restrict__ dst,
                           int n4) {
    int i = blockIdx.x * blockDim.x + threadIdx.x;
    if (i < n4) {
        float4 v = reinterpret_cast<const float4*>(src)[i];
        v.x = f2tf32(v.x); v.y = f2tf32(v.y); v.z = f2tf32(v.z); v.w = f2tf32(v.w);
        reinterpret_cast<float4*>(dst)[i] = v;
    }
}

// ---------------- state zero + barrier reset --------------------------------
__global__ void zero_state(float* __restrict__ h, unsigned* __restrict__ bar) {
    int i = blockIdx.x * blockDim.x + threadIdx.x;
    if (i < 2 * BH) h[i] = 0.f;
    if (i == 0) *bar = 0u;
}

// ---------------- pipelined TF32 GEMM: C = A@B + bias -----------------------
// A [M,lda] row-major (pre-rounded tf32), B [K,ldb] row-major (pre-rounded).
// 128x256 tiles, 512 threads, 3-stage cp.async pipeline (K-stage 32),
// supertile swizzle. One __syncthreads per K=32.
__global__ __launch_bounds__(512, 1) void gemm_tf32_pipe(
    const float* __restrict__ A, int lda,
    const float* __restrict__ Bm, int ldb,
    const float* __restrict__ bias,
    float* __restrict__ C, int ldc, int K, int ntiles, int mtiles)
{
    extern __shared__ float sm[];

    // supertile swizzle: consecutive blocks share an L2-resident A/B slab
    int lin = blockIdx.x;
    int n_t, m_t;
    {
        int full = ntiles / GSW;
        int blocksFull = full * GSW * mtiles;
        if (lin < blocksFull) {
            int sid = lin / (GSW * mtiles);
            int r = lin - sid * (GSW * mtiles);
            n_t = sid * GSW + (r % GSW);
            m_t = r / GSW;
        } else {
            int r = lin - blocksFull;
            int wd = ntiles - full * GSW;
            n_t = full * GSW + (r % wd);
            m_t = r / wd;
        }
    }
    const int n0 = n_t * GBN;
    const int m0 = m_t * GBM;

    const int tid = threadIdx.x;
    const int lane = tid & 31, warp = tid >> 5;
    const int wm = (warp & 3) * 32;
    const int wn = (warp >> 2) * 64;
    const int g = lane >> 2, tig = lane & 3;

    const uint32_t sm_u32 = (uint32_t)__cvta_generic_to_shared(sm);

    float acc[2][8][4];
#pragma unroll
    for (int i = 0; i < 2; i++)
#pragma unroll
        for (int j = 0; j < 8; j++)
#pragma unroll
            for (int r = 0; r < 4; r++) acc[i][j][r] = 0.f;

    auto issue_stage = [&](int kb, int s) {
        int k0 = kb * GBK;
        uint32_t aS = sm_u32 + (uint32_t)(s * STAGE_FLOATS) * 4;
        uint32_t bS = aS + A_STAGE * 4;
#pragma unroll
        for (int i = 0; i < 2; i++) {               // A: 1024 cp16
            int idx = tid + i * 512;
            int row = idx >> 3, kq = (idx & 7) << 2;
            cp16(aS + (uint32_t)(row * ASTRIDE + kq) * 4,
                 A + (size_t)(m0 + row) * lda + k0 + kq);
        }
#pragma unroll
        for (int i = 0; i < 4; i++) {               // B: 2048 cp16
            int idx = tid + i * 512;
            int k = idx >> 6, nq = (idx & 63) << 2;
            cp16(bS + (uint32_t)(k * BSTRIDE + nq) * 4,
                 Bm + (size_t)(k0 + k) * ldb + n0 + nq);
        }
        CP_COMMIT();
    };
    auto compute_stage = [&](int s) {
        const float* aS = sm + s * STAGE_FLOATS;
        const float* bS = aS + A_STAGE;
#pragma unroll
        for (int ks = 0; ks < GBK; ks += 8) {
            uint32_t af[2][4];
#pragma unroll
            for (int mt = 0; mt < 2; mt++) {
                int mb = wm + mt * 16 + g;
                af[mt][0] = __float_as_uint(aS[mb * ASTRIDE + ks + tig]);
                af[mt][1] = __float_as_uint(aS[(mb + 8) * ASTRIDE + ks + tig]);
                af[mt][2] = __float_as_uint(aS[mb * ASTRIDE + ks + tig + 4]);
                af[mt][3] = __float_as_uint(aS[(mb + 8) * ASTRIDE + ks + tig + 4]);
            }
#pragma unroll
            for (int nt = 0; nt < 8; nt++) {
                int nb = wn + nt * 8 + g;
                uint32_t bf[2];
                bf[0] = __float_as_uint(bS[(ks + tig) * BSTRIDE + nb]);
                bf[1] = __float_as_uint(bS[(ks + tig + 4) * BSTRIDE + nb]);
                mma_tf32(acc[0][nt], af[0], bf);
                mma_tf32(acc[1][nt], af[1], bf);
            }
        }
    };

    const int nk = K >> 5;
    issue_stage(0, 0);
    issue_stage(1, 1);
    int s = 0;
    for (int kb = 0; kb < nk; kb++) {
        if (kb < nk - 1) { CP_WAIT(1); } else { CP_WAIT(0); }
        __syncthreads();
        compute_stage(s);
        if (kb + 2 < nk) {
            int nb = s + 2; if (nb >= 3) nb -= 3;
            issue_stage(kb + 2, nb);
        }
        s = s + 1; if (s == 3) s = 0;
    }

#pragma unroll
    for (int mt = 0; mt < 2; mt++) {
        int m = m0 + wm + mt * 16 + g;
#pragma unroll
        for (int nt = 0; nt < 8; nt++) {
            int n = n0 + wn + nt * 8 + 2 * tig;
            float bx = bias[n], by = bias[n + 1];
            float2 v0 = make_float2(acc[mt][nt][0] + bx, acc[mt][nt][1] + by);
            float2 v1 = make_float2(acc[mt][nt][2] + bx, acc[mt][nt][3] + by);
            *reinterpret_cast<float2*>(C + (size_t)m * ldc + n) = v0;
            *reinterpret_cast<float2*>(C + (size_t)(m + 8) * ldc + n) = v1;
        }
    }
}

// ---------------- persistent LSTM layer (central barrier; measured best) ----
#define WHS_BYTES 131072
#define HB_BYTES  (NW * 2 * CBYTES)
#define SMEM_PERSIST (WHS_BYTES + HB_BYTES)

__global__ __launch_bounds__(256, 1) void lstm_persist(
    const float* __restrict__ Xg,
    const float* __restrict__ Wh,
    float* __restrict__ hbuf,
    float* __restrict__ Hout,
    unsigned* __restrict__ bar)
{
    extern __shared__ char smx[];
    float2* Whs = reinterpret_cast<float2*>(smx);
    float*  scr = reinterpret_cast<float*>(smx + WHS_BYTES);

    const int tid = threadIdx.x;
    const int lane = tid & 31, warp = tid >> 5;
    const int g = lane >> 2, tig = lane & 3;
    const int u0 = blockIdx.x * UPB;

    const uint32_t smem_u32 = (uint32_t)__cvta_generic_to_shared(smx);
    const uint32_t hb_u32 = smem_u32 + WHS_BYTES + warp * 2 * CBYTES;
    float* hb_gen = reinterpret_cast<float*>(smx + WHS_BYTES + warp * 2 * CBYTES);

    for (int ko = warp; ko < 128; ko += NW) {
#pragma unroll
        for (int nt = 0; nt < 4; nt++) {
            int col = nt * HID_ + u0 + g;
            float b0 = Wh[(size_t)(ko * 8 + tig) * G_ + col];
            float b1 = Wh[(size_t)(ko * 8 + tig + 4) * G_ + col];
            Whs[(ko * 4 + nt) * 32 + lane] = make_float2(f2tf32(b0), f2tf32(b1));
        }
    }
    __syncthreads();

    const int pm = tid >> 3, pul = tid & 7;
    const int pmt = pm >> 4;
    const int pgg = (pm & 15) & 7, phi = (pm & 15) >> 3;
    const int pr = phi * 2 + (pul & 1);
    const int pln = pgg * 4 + (pul >> 1);
    const size_t xgbase = (size_t)pm * G_ + u0 + pul;

    const int r8 = lane >> 3, kk = lane & 7;
    const int kw = warp * 128;

    float creg = 0.f;
    float xr[4];
#pragma unroll
    for (int s = 0; s < 4; s++) xr[s] = Xg[xgbase + s * HID_];

    for (int t = 0; t < T_; t++) {
        const float* hin = hbuf + (t & 1) * BH;
        float* hnx = hbuf + ((t + 1) & 1) * BH;

        float acc[2][4][4];
#pragma unroll
        for (int mt = 0; mt < 2; mt++)
#pragma unroll
            for (int nt = 0; nt < 4; nt++)
#pragma unroll
                for (int r = 0; r < 4; r++) acc[mt][nt][r] = 0.f;

        auto cp_chunk = [&](int c, int b) {
            const int kbase = kw + c * CHK;
            const uint32_t dbase = hb_u32 + b * CBYTES + (kk * 4) * 4;
            const float* sbase = hin + r8 * HID_ + kbase + kk * 4;
#pragma unroll
            for (int p = 0; p < 8; p++) {
                int row4 = p * 4;
                cp16(dbase + (uint32_t)((row4 + r8) * CSTRIDE) * 4,
                     sbase + (size_t)row4 * HID_);
            }
            CP_COMMIT();
        };
        auto compute_chunk = [&](int c, int b) {
            const float* buf = hb_gen + b * (CBYTES / 4);
#pragma unroll
            for (int k8 = 0; k8 < 4; k8++) {
                int ko = warp * 16 + c * 4 + k8;
                int kA = k8 * 8 + tig;
                uint32_t af[2][4];
#pragma unroll
                for (int mt = 0; mt < 2; mt++) {
                    int mb = mt * 16;
                    af[mt][0] = __float_as_uint(buf[(mb + g) * CSTRIDE + kA]);
                    af[mt][1] = __float_as_uint(buf[(mb + g + 8) * CSTRIDE + kA]);
                    af[mt][2] = __float_as_uint(buf[(mb + g) * CSTRIDE + kA + 4]);
                    af[mt][3] = __float_as_uint(buf[(mb + g + 8) * CSTRIDE + kA + 4]);
                }
#pragma unroll
                for (int nt = 0; nt < 4; nt++) {
                    float2 bb = Whs[(ko * 4 + nt) * 32 + lane];
                    uint32_t bf[2] = {__float_as_uint(bb.x), __float_as_uint(bb.y)};
                    mma_tf32(acc[0][nt], af[0], bf);
                    mma_tf32(acc[1][nt], af[1], bf);
                }
            }
        };

        cp_chunk(0, 0);
        cp_chunk(1, 1);
        CP_WAIT(1); __syncwarp();
        compute_chunk(0, 0);
        cp_chunk(2, 0);
        CP_WAIT(1); __syncwarp();
        compute_chunk(1, 1);
        cp_chunk(3, 1);
        CP_WAIT(1); __syncwarp();
        compute_chunk(2, 0);
        CP_WAIT(0); __syncwarp();
        compute_chunk(3, 1);

        __syncthreads();
#pragma unroll
        for (int mt = 0; mt < 2; mt++)
#pragma unroll
            for (int nt = 0; nt < 4; nt++)
#pragma unroll
                for (int r = 0; r < 4; r++) {
                    int ridx = mt * 16 + nt * 4 + r;
                    scr[((warp * 32 + ridx) << 5) + lane] = acc[mt][nt][r];
                }
        __syncthreads();

        float hh;
        {
            float gv[4];
#pragma unroll
            for (int s = 0; s < 4; s++) {
                int ridx = pmt * 16 + s * 4 + pr;
                float v = 0.f;
#pragma unroll
                for (int w = 0; w < NW; w++)
                    v += scr[((w * 32 + ridx) << 5) + pln];
                gv[s] = v + xr[s];
            }
            float cc = creg;
            cc = sigm(gv[2] + 1.f) * cc + sigm(gv[0]) * tanhf(gv[1]);
            hh = sigm(gv[3]) * tanhf(cc);
            creg = cc;
            hnx[pm * HID_ + u0 + pul] = f2tf32(hh);
        }

        if (t < T_ - 1) {
            __syncthreads();
            if (tid == 0) {
                __threadfence();
                atomicAdd(bar, 1u);
            }
            Hout[((size_t)(t * B_ + pm)) * HID_ + u0 + pul] = f2tf32(hh);
            const size_t xb = xgbase + (size_t)(t + 1) * B_ * G_;
#pragma unroll
            for (int s = 0; s < 4; s++) xr[s] = Xg[xb + s * HID_];
            if (tid == 0) {
                unsigned target = (unsigned)(t + 1) * NBLK;
                while (ld_acq(bar) < target) { }
            }
            __syncthreads();
        } else {
            Hout[((size_t)(t * B_ + pm)) * HID_ + u0 + pul] = f2tf32(hh);
        }
    }
}

// ---------------- launch ----------------------------------------------------
extern "C" void kernel_launch(void* const* d_in, const int* in_sizes, int n_in,
                              void* d_out, int out_size) {
    const int*   data = (const int*)d_in[0];
    const float* emb  = (const float*)d_in[2];
    const float* W0   = (const float*)d_in[3];
    const float* b0   = (const float*)d_in[4];
    const float* W1   = (const float*)d_in[5];
    const float* b1   = (const float*)d_in[6];
    const float* W2   = (const float*)d_in[7];
    const float* b2   = (const float*)d_in[8];
    const float* Wd   = (const float*)d_in[9];
    const float* bd   = (const float*)d_in[10];
    float* out = (float*)d_out;
    (void)in_sizes; (void)n_in; (void)out_size;

    float *X0, *HA, *HB, *Xg, *Wr, *h;
    unsigned* bar;
    cudaGetSymbolAddress((void**)&X0, g_X0);
    cudaGetSymbolAddress((void**)&HA, g_HA);
    cudaGetSymbolAddress((void**)&HB, g_HB);
    cudaGetSymbolAddress((void**)&Xg, g_Xg);
    cudaGetSymbolAddress((void**)&Wr, g_Wr);
    cudaGetSymbolAddress((void**)&h,  g_h);
    cudaGetSymbolAddress((void**)&bar, g_bar);

    cudaFuncSetAttribute(lstm_persist, cudaFuncAttributeMaxDynamicSharedMemorySize,
                         SMEM_PERSIST);
    cudaFuncSetAttribute(gemm_tf32_pipe, cudaFuncAttributeMaxDynamicSharedMemorySize,
                         GEMM_SMEM);

    gather_kernel<<<TB_, 128>>>(data, emb, X0);

    const int zgrid = (2 * BH + 255) / 256;
    const int MT = TB_ / GBM;          // 64

    // layer 0 (Din = 512)
    round_copy<<<(EMB_ * G_ / 4 + 255) / 256, 256>>>(W0, Wr, EMB_ * G_ / 4);
    zero_state<<<zgrid, 256>>>(h, bar);
    gemm_tf32_pipe<<<MT * (G_ / GBN), 512, GEMM_SMEM>>>(
        X0, EMB_, Wr, G_, b0, Xg, G_, EMB_, G_ / GBN, MT);
    lstm_persist<<<NBLK, 256, SMEM_PERSIST>>>(Xg, W0 + (size_t)EMB_ * G_, h, HA, bar);

    // layer 1
    round_copy<<<(HID_ * G_ / 4 + 255) / 256, 256>>>(W1, Wr, HID_ * G_ / 4);
    zero_state<<<zgrid, 256>>>(h, bar);
    gemm_tf32_pipe<<<MT * (G_ / GBN), 512, GEMM_SMEM>>>(
        HA, HID_, Wr, G_, b1, Xg, G_, HID_, G_ / GBN, MT);
    lstm_persist<<<NBLK, 256, SMEM_PERSIST>>>(Xg, W1 + (size_t)HID_ * G_, h, HB, bar);

    // layer 2
    round_copy<<<(HID_ * G_ / 4 + 255) / 256, 256>>>(W2, Wr, HID_ * G_ / 4);
    zero_state<<<zgrid, 256>>>(h, bar);
    gemm_tf32_pipe<<<MT * (G_ / GBN), 512, GEMM_SMEM>>>(
        HB, HID_, Wr, G_, b2, Xg, G_, HID_, G_ / GBN, MT);
    lstm_persist<<<NBLK, 256, SMEM_PERSIST>>>(Xg, W2 + (size_t)HID_ * G_, h, HA, bar);

    // projection: round Wd into the now-dead Xg buffer, then GEMM
    round_copy<<<(HID_ * VOCAB_ / 4 + 255) / 256, 256>>>(Wd, Xg, HID_ * VOCAB_ / 4);
    gemm_tf32_pipe<<<MT * (VOCAB_ / GBN), 512, GEMM_SMEM>>>(
        HA, HID_, Xg, VOCAB_, bd, out, VOCAB_, HID_, VOCAB_ / GBN, MT);
}

// round 10
// speedup vs baseline: 1.2727x; 1.0183x over previous
#include <cuda_runtime.h>
#include <cstdint>
#include <math.h>

#define T_     256
#define B_     32
#define VOCAB_ 32000
#define EMB_   512
#define HID_   1024
#define G_     4096   // 4*HID
#define TB_    8192   // T_*B_
#define NBLK   128    // persistent blocks (1 per SM)
#define UPB    8      // hidden units per block (128*8 = 1024)
#define BH     (B_ * HID_)
#define NW     8      // warps per block in lstm_persist

// persistent-kernel chunking
#define CHK    32
#define CSTRIDE 36
#define CBYTES (32 * CSTRIDE * 4)

// pipelined GEMM config (K-stage = 32, 8 warps, 64x64 warp tiles)
#define GBM 128
#define GBN 256
#define GBK 32
#define ASTRIDE 36                    // A smem row stride (floats)
#define BSTRIDE 264                   // B smem k-row stride (floats)
#define A_STAGE (GBM * ASTRIDE)       // 4608 floats
#define B_STAGE (GBK * BSTRIDE)       // 8448 floats
#define STAGE_FLOATS (A_STAGE + B_STAGE)
#define GEMM_SMEM (3 * STAGE_FLOATS * 4)   // 156672 B
#define GSW 8                          // supertile width (N tiles)

// ---------------- scratch (device globals; no allocations allowed) ----------
__device__ float g_X0[TB_ * EMB_];
__device__ float g_HA[TB_ * HID_];
__device__ float g_HB[TB_ * HID_];
__device__ float g_Xg[(size_t)TB_ * G_];   // also reused for rounded Wd
__device__ float g_Wr[HID_ * G_];          // rounded pre-gate weights (16.8 MB)
__device__ float g_h[2 * BH];
__device__ unsigned g_bar;

// ---------------- helpers ---------------------------------------------------
__device__ __forceinline__ float f2tf32(float x) {
    uint32_t u;
    asm("cvt.rna.tf32.f32 %0, %1;" : "=r"(u) : "f"(x));
    return __uint_as_float(u);
}

__device__ __forceinline__ void mma_tf32(float* d, const uint32_t* a, const uint32_t* b) {
    asm volatile(
        "mma.sync.aligned.m16n8k8.row.col.f32.tf32.tf32.f32 "
        "{%0,%1,%2,%3}, {%4,%5,%6,%7}, {%8,%9}, {%0,%1,%2,%3};\n"
        : "+f"(d[0]), "+f"(d[1]), "+f"(d[2]), "+f"(d[3])
        : "r"(a[0]), "r"(a[1]), "r"(a[2]), "r"(a[3]), "r"(b[0]), "r"(b[1]));
}

__device__ __forceinline__ float sigm(float x) { return 1.f / (1.f + expf(-x)); }

__device__ __forceinline__ unsigned ld_acq(const unsigned* p) {
    unsigned v;
    asm volatile("ld.acquire.gpu.u32 %0, [%1];" : "=r"(v) : "l"(p) : "memory");
    return v;
}

__device__ __forceinline__ void cp16(uint32_t dst, const void* src) {
    asm volatile("cp.async.cg.shared.global [%0], [%1], 16;" :: "r"(dst), "l"(src));
}
#define CP_COMMIT() asm volatile("cp.async.commit_group;")
#define CP_WAIT(N)  asm volatile("cp.async.wait_group %0;" :: "n"(N))

// ---------------- embedding gather (tf32-rounded) ---------------------------
__global__ void gather_kernel(const int* __restrict__ data,
                              const float* __restrict__ emb,
                              float* __restrict__ X0) {
    int tb = blockIdx.x;
    int idx = data[tb];
    const float4* src = reinterpret_cast<const float4*>(emb + (size_t)idx * EMB_);
    float4* dst = reinterpret_cast<float4*>(X0 + (size_t)tb * EMB_);
    float4 v = src[threadIdx.x];
    v.x = f2tf32(v.x); v.y = f2tf32(v.y); v.z = f2tf32(v.z); v.w = f2tf32(v.w);
    dst[threadIdx.x] = v;
}

// ---------------- tf32 round-copy (weights) ---------------------------------
__global__ void round_copy(const float* __restrict__ src, float* __restrict__ dst,
                           int n4) {
    int i = blockIdx.x * blockDim.x + threadIdx.x;
    if (i < n4) {
        float4 v = reinterpret_cast<const float4*>(src)[i];
        v.x = f2tf32(v.x); v.y = f2tf32(v.y); v.z = f2tf32(v.z); v.w = f2tf32(v.w);
        reinterpret_cast<float4*>(dst)[i] = v;
    }
}

// ---------------- state zero + barrier reset --------------------------------
__global__ void zero_state(float* __restrict__ h, unsigned* __restrict__ bar) {
    int i = blockIdx.x * blockDim.x + threadIdx.x;
    if (i < 2 * BH) h[i] = 0.f;
    if (i == 0) *bar = 0u;
}

// ---------------- pipelined TF32 GEMM: C = A@B + bias -----------------------
// A [M,lda] row-major (pre-rounded tf32), B [K,ldb] row-major (pre-rounded).
// 128x256 block tile, 256 threads (8 warps, 64x64 warp tiles),
// 3-stage cp.async pipeline (K-stage 32), supertile swizzle.
__global__ __launch_bounds__(256, 1) void gemm_tf32_pipe(
    const float* __restrict__ A, int lda,
    const float* __restrict__ Bm, int ldb,
    const float* __restrict__ bias,
    float* __restrict__ C, int ldc, int K, int ntiles, int mtiles)
{
    extern __shared__ float sm[];

    // supertile swizzle: consecutive blocks share an L2-resident A/B slab
    int lin = blockIdx.x;
    int n_t, m_t;
    {
        int full = ntiles / GSW;
        int blocksFull = full * GSW * mtiles;
        if (lin < blocksFull) {
            int sid = lin / (GSW * mtiles);
            int r = lin - sid * (GSW * mtiles);
            n_t = sid * GSW + (r % GSW);
            m_t = r / GSW;
        } else {
            int r = lin - blocksFull;
            int wd = ntiles - full * GSW;
            n_t = full * GSW + (r % wd);
            m_t = r / wd;
        }
    }
    const int n0 = n_t * GBN;
    const int m0 = m_t * GBM;

    const int tid = threadIdx.x;
    const int lane = tid & 31, warp = tid >> 5;
    const int wm = (warp & 1) * 64;       // 2 M groups
    const int wn = (warp >> 1) * 64;      // 4 N groups
    const int g = lane >> 2, tig = lane & 3;

    const uint32_t sm_u32 = (uint32_t)__cvta_generic_to_shared(sm);

    float acc[4][8][4];
#pragma unroll
    for (int i = 0; i < 4; i++)
#pragma unroll
        for (int j = 0; j < 8; j++)
#pragma unroll
            for (int r = 0; r < 4; r++) acc[i][j][r] = 0.f;

    auto issue_stage = [&](int kb, int s) {
        int k0 = kb * GBK;
        uint32_t aS = sm_u32 + (uint32_t)(s * STAGE_FLOATS) * 4;
        uint32_t bS = aS + A_STAGE * 4;
#pragma unroll
        for (int i = 0; i < 4; i++) {               // A: 1024 cp16
            int idx = tid + i * 256;
            int row = idx >> 3, kq = (idx & 7) << 2;
            cp16(aS + (uint32_t)(row * ASTRIDE + kq) * 4,
                 A + (size_t)(m0 + row) * lda + k0 + kq);
        }
#pragma unroll
        for (int i = 0; i < 8; i++) {               // B: 2048 cp16
            int idx = tid + i * 256;
            int k = idx >> 6, nq = (idx & 63) << 2;
            cp16(bS + (uint32_t)(k * BSTRIDE + nq) * 4,
                 Bm + (size_t)(k0 + k) * ldb + n0 + nq);
        }
        CP_COMMIT();
    };
    auto compute_stage = [&](int s) {
        const float* aS = sm + s * STAGE_FLOATS;
        const float* bS = aS + A_STAGE;
#pragma unroll
        for (int ks = 0; ks < GBK; ks += 8) {
            uint32_t af[4][4];
#pragma unroll
            for (int mt = 0; mt < 4; mt++) {
                int mb = wm + mt * 16 + g;
                af[mt][0] = __float_as_uint(aS[mb * ASTRIDE + ks + tig]);
                af[mt][1] = __float_as_uint(aS[(mb + 8) * ASTRIDE + ks + tig]);
                af[mt][2] = __float_as_uint(aS[mb * ASTRIDE + ks + tig + 4]);
                af[mt][3] = __float_as_uint(aS[(mb + 8) * ASTRIDE + ks + tig + 4]);
            }
#pragma unroll
            for (int nt = 0; nt < 8; nt++) {
                int nb = wn + nt * 8 + g;
                uint32_t bf[2];
                bf[0] = __float_as_uint(bS[(ks + tig) * BSTRIDE + nb]);
                bf[1] = __float_as_uint(bS[(ks + tig + 4) * BSTRIDE + nb]);
#pragma unroll
                for (int mt = 0; mt < 4; mt++)
                    mma_tf32(acc[mt][nt], af[mt], bf);
            }
        }
    };

    const int nk = K >> 5;
    issue_stage(0, 0);
    issue_stage(1, 1);
    int s = 0;
    for (int kb = 0; kb < nk; kb++) {
        if (kb < nk - 1) { CP_WAIT(1); } else { CP_WAIT(0); }
        __syncthreads();
        compute_stage(s);
        if (kb + 2 < nk) {
            int nb = s + 2; if (nb >= 3) nb -= 3;
            issue_stage(kb + 2, nb);
        }
        s = s + 1; if (s == 3) s = 0;
    }

#pragma unroll
    for (int mt = 0; mt < 4; mt++) {
        int m = m0 + wm + mt * 16 + g;
#pragma unroll
        for (int nt = 0; nt < 8; nt++) {
            int n = n0 + wn + nt * 8 + 2 * tig;
            float bx = bias[n], by = bias[n + 1];
            float2 v0 = make_float2(acc[mt][nt][0] + bx, acc[mt][nt][1] + by);
            float2 v1 = make_float2(acc[mt][nt][2] + bx, acc[mt][nt][3] + by);
            *reinterpret_cast<float2*>(C + (size_t)m * ldc + n) = v0;
            *reinterpret_cast<float2*>(C + (size_t)(m + 8) * ldc + n) = v1;
        }
    }
}

// ---------------- persistent LSTM layer (central barrier; measured best) ----
#define WHS_BYTES 131072
#define HB_BYTES  (NW * 2 * CBYTES)
#define SMEM_PERSIST (WHS_BYTES + HB_BYTES)

__global__ __launch_bounds__(256, 1) void lstm_persist(
    const float* __restrict__ Xg,
    const float* __restrict__ Wh,
    float* __restrict__ hbuf,
    float* __restrict__ Hout,
    unsigned* __restrict__ bar)
{
    extern __shared__ char smx[];
    float2* Whs = reinterpret_cast<float2*>(smx);
    float*  scr = reinterpret_cast<float*>(smx + WHS_BYTES);

    const int tid = threadIdx.x;
    const int lane = tid & 31, warp = tid >> 5;
    const int g = lane >> 2, tig = lane & 3;
    const int u0 = blockIdx.x * UPB;

    const uint32_t smem_u32 = (uint32_t)__cvta_generic_to_shared(smx);
    const uint32_t hb_u32 = smem_u32 + WHS_BYTES + warp * 2 * CBYTES;
    float* hb_gen = reinterpret_cast<float*>(smx + WHS_BYTES + warp * 2 * CBYTES);

    for (int ko = warp; ko < 128; ko += NW) {
#pragma unroll
        for (int nt = 0; nt < 4; nt++) {
            int col = nt * HID_ + u0 + g;
            float b0 = Wh[(size_t)(ko * 8 + tig) * G_ + col];
            float b1 = Wh[(size_t)(ko * 8 + tig + 4) * G_ + col];
            Whs[(ko * 4 + nt) * 32 + lane] = make_float2(f2tf32(b0), f2tf32(b1));
        }
    }
    __syncthreads();

    const int pm = tid >> 3, pul = tid & 7;
    const int pmt = pm >> 4;
    const int pgg = (pm & 15) & 7, phi = (pm & 15) >> 3;
    const int pr = phi * 2 + (pul & 1);
    const int pln = pgg * 4 + (pul >> 1);
    const size_t xgbase = (size_t)pm * G_ + u0 + pul;

    const int r8 = lane >> 3, kk = lane & 7;
    const int kw = warp * 128;

    float creg = 0.f;
    float xr[4];
#pragma unroll
    for (int s = 0; s < 4; s++) xr[s] = Xg[xgbase + s * HID_];

    for (int t = 0; t < T_; t++) {
        const float* hin = hbuf + (t & 1) * BH;
        float* hnx = hbuf + ((t + 1) & 1) * BH;

        float acc[2][4][4];
#pragma unroll
        for (int mt = 0; mt < 2; mt++)
#pragma unroll
            for (int nt = 0; nt < 4; nt++)
#pragma unroll
                for (int r = 0; r < 4; r++) acc[mt][nt][r] = 0.f;

        auto cp_chunk = [&](int c, int b) {
            const int kbase = kw + c * CHK;
            const uint32_t dbase = hb_u32 + b * CBYTES + (kk * 4) * 4;
            const float* sbase = hin + r8 * HID_ + kbase + kk * 4;
#pragma unroll
            for (int p = 0; p < 8; p++) {
                int row4 = p * 4;
                cp16(dbase + (uint32_t)((row4 + r8) * CSTRIDE) * 4,
                     sbase + (size_t)row4 * HID_);
            }
            CP_COMMIT();
        };
        auto compute_chunk = [&](int c, int b) {
            const float* buf = hb_gen + b * (CBYTES / 4);
#pragma unroll
            for (int k8 = 0; k8 < 4; k8++) {
                int ko = warp * 16 + c * 4 + k8;
                int kA = k8 * 8 + tig;
                uint32_t af[2][4];
#pragma unroll
                for (int mt = 0; mt < 2; mt++) {
                    int mb = mt * 16;
                    af[mt][0] = __float_as_uint(buf[(mb + g) * CSTRIDE + kA]);
                    af[mt][1] = __float_as_uint(buf[(mb + g + 8) * CSTRIDE + kA]);
                    af[mt][2] = __float_as_uint(buf[(mb + g) * CSTRIDE + kA + 4]);
                    af[mt][3] = __float_as_uint(buf[(mb + g + 8) * CSTRIDE + kA + 4]);
                }
#pragma unroll
                for (int nt = 0; nt < 4; nt++) {
                    float2 bb = Whs[(ko * 4 + nt) * 32 + lane];
                    uint32_t bf[2] = {__float_as_uint(bb.x), __float_as_uint(bb.y)};
                    mma_tf32(acc[0][nt], af[0], bf);
                    mma_tf32(acc[1][nt], af[1], bf);
                }
            }
        };

        cp_chunk(0, 0);
        cp_chunk(1, 1);
        CP_WAIT(1); __syncwarp();
        compute_chunk(0, 0);
        cp_chunk(2, 0);
        CP_WAIT(1); __syncwarp();
        compute_chunk(1, 1);
        cp_chunk(3, 1);
        CP_WAIT(1); __syncwarp();
        compute_chunk(2, 0);
        CP_WAIT(0); __syncwarp();
        compute_chunk(3, 1);

        __syncthreads();
#pragma unroll
        for (int mt = 0; mt < 2; mt++)
#pragma unroll
            for (int nt = 0; nt < 4; nt++)
#pragma unroll
                for (int r = 0; r < 4; r++) {
                    int ridx = mt * 16 + nt * 4 + r;
                    scr[((warp * 32 + ridx) << 5) + lane] = acc[mt][nt][r];
                }
        __syncthreads();

        float hh;
        {
            float gv[4];
#pragma unroll
            for (int s = 0; s < 4; s++) {
                int ridx = pmt * 16 + s * 4 + pr;
                float v = 0.f;
#pragma unroll
                for (int w = 0; w < NW; w++)
                    v += scr[((w * 32 + ridx) << 5) + pln];
                gv[s] = v + xr[s];
            }
            float cc = creg;
            cc = sigm(gv[2] + 1.f) * cc + sigm(gv[0]) * tanhf(gv[1]);
            hh = sigm(gv[3]) * tanhf(cc);
            creg = cc;
            hnx[pm * HID_ + u0 + pul] = f2tf32(hh);
        }

        if (t < T_ - 1) {
            __syncthreads();
            if (tid == 0) {
                __threadfence();
                atomicAdd(bar, 1u);
            }
            Hout[((size_t)(t * B_ + pm)) * HID_ + u0 + pul] = f2tf32(hh);
            const size_t xb = xgbase + (size_t)(t + 1) * B_ * G_;
#pragma unroll
            for (int s = 0; s < 4; s++) xr[s] = Xg[xb + s * HID_];
            if (tid == 0) {
                unsigned target = (unsigned)(t + 1) * NBLK;
                while (ld_acq(bar) < target) { }
            }
            __syncthreads();
        } else {
            Hout[((size_t)(t * B_ + pm)) * HID_ + u0 + pul] = f2tf32(hh);
        }
    }
}

// ---------------- launch ----------------------------------------------------
extern "C" void kernel_launch(void* const* d_in, const int* in_sizes, int n_in,
                              void* d_out, int out_size) {
    const int*   data = (const int*)d_in[0];
    const float* emb  = (const float*)d_in[2];
    const float* W0   = (const float*)d_in[3];
    const float* b0   = (const float*)d_in[4];
    const float* W1   = (const float*)d_in[5];
    const float* b1   = (const float*)d_in[6];
    const float* W2   = (const float*)d_in[7];
    const float* b2   = (const float*)d_in[8];
    const float* Wd   = (const float*)d_in[9];
    const float* bd   = (const float*)d_in[10];
    float* out = (float*)d_out;
    (void)in_sizes; (void)n_in; (void)out_size;

    float *X0, *HA, *HB, *Xg, *Wr, *h;
    unsigned* bar;
    cudaGetSymbolAddress((void**)&X0, g_X0);
    cudaGetSymbolAddress((void**)&HA, g_HA);
    cudaGetSymbolAddress((void**)&HB, g_HB);
    cudaGetSymbolAddress((void**)&Xg, g_Xg);
    cudaGetSymbolAddress((void**)&Wr, g_Wr);
    cudaGetSymbolAddress((void**)&h,  g_h);
    cudaGetSymbolAddress((void**)&bar, g_bar);

    cudaFuncSetAttribute(lstm_persist, cudaFuncAttributeMaxDynamicSharedMemorySize,
                         SMEM_PERSIST);
    cudaFuncSetAttribute(gemm_tf32_pipe, cudaFuncAttributeMaxDynamicSharedMemorySize,
                         GEMM_SMEM);

    gather_kernel<<<TB_, 128>>>(data, emb, X0);

    const int zgrid = (2 * BH + 255) / 256;
    const int MT = TB_ / GBM;          // 64

    // layer 0 (Din = 512)
    round_copy<<<(EMB_ * G_ / 4 + 255) / 256, 256>>>(W0, Wr, EMB_ * G_ / 4);
    zero_state<<<zgrid, 256>>>(h, bar);
    gemm_tf32_pipe<<<MT * (G_ / GBN), 256, GEMM_SMEM>>>(
        X0, EMB_, Wr, G_, b0, Xg, G_, EMB_, G_ / GBN, MT);
    lstm_persist<<<NBLK, 256, SMEM_PERSIST>>>(Xg, W0 + (size_t)EMB_ * G_, h, HA, bar);

    // layer 1
    round_copy<<<(HID_ * G_ / 4 + 255) / 256, 256>>>(W1, Wr, HID_ * G_ / 4);
    zero_state<<<zgrid, 256>>>(h, bar);
    gemm_tf32_pipe<<<MT * (G_ / GBN), 256, GEMM_SMEM>>>(
        HA, HID_, Wr, G_, b1, Xg, G_, HID_, G_ / GBN, MT);
    lstm_persist<<<NBLK, 256, SMEM_PERSIST>>>(Xg, W1 + (size_t)HID_ * G_, h, HB, bar);

    // layer 2
    round_copy<<<(HID_ * G_ / 4 + 255) / 256, 256>>>(W2, Wr, HID_ * G_ / 4);
    zero_state<<<zgrid, 256>>>(h, bar);
    gemm_tf32_pipe<<<MT * (G_ / GBN), 256, GEMM_SMEM>>>(
        HB, HID_, Wr, G_, b2, Xg, G_, HID_, G_ / GBN, MT);
    lstm_persist<<<NBLK, 256, SMEM_PERSIST>>>(Xg, W2 + (size_t)HID_ * G_, h, HA, bar);

    // projection: round Wd into the now-dead Xg buffer, then GEMM
    round_copy<<<(HID_ * VOCAB_ / 4 + 255) / 256, 256>>>(Wd, Xg, HID_ * VOCAB_ / 4);
    gemm_tf32_pipe<<<MT * (VOCAB_ / GBN), 256, GEMM_SMEM>>>(
        HA, HID_, Xg, VOCAB_, bd, out, VOCAB_, HID_, VOCAB_ / GBN, MT);
}

// round 11
// speedup vs baseline: 1.6852x; 1.3242x over previous
#include <cuda_runtime.h>
#include <cuda_fp16.h>
#include <cstdint>
#include <math.h>

#define T_     256
#define B_     32
#define VOCAB_ 32000
#define EMB_   512
#define HID_   1024
#define G_     4096   // 4*HID
#define TB_    8192   // T_*B_
#define NBLK   128    // persistent blocks (1 per SM)
#define UPB    8      // hidden units per block (128*8 = 1024)
#define BH     (B_ * HID_)
#define NW     8      // warps per block in lstm_persist

// persistent-kernel chunking
#define CHK    32
#define CSTRIDE 36
#define CBYTES (32 * CSTRIDE * 4)

// fp16 pipelined GEMM config (K-stage = 64, 8 warps, 64x64 warp tiles)
#define GBM 128
#define GBN 256
#define GBK 64
#define ASTH 72                        // A smem row stride (halves)
#define BSTH 72                        // B smem row stride (halves)
#define A_STAGE_H (GBM * ASTH)         // 9216 halves
#define B_STAGE_H (GBN * BSTH)         // 18432 halves
#define STAGE_H (A_STAGE_H + B_STAGE_H)
#define GEMM_SMEM (3 * STAGE_H * 2)    // 165888 B
#define GSW 8                          // supertile width (N tiles)

// ---------------- scratch (device globals; no allocations allowed) ----------
__device__ float g_X0[TB_ * EMB_];         // used as half[TB][EMB]
__device__ float g_HA[TB_ * HID_];         // used as half[TB][HID]
__device__ float g_HB[TB_ * HID_];         // used as half[TB][HID]
__device__ float g_Xg[(size_t)TB_ * G_];   // f32 gate priors; later WdT half
__device__ float g_Wr[HID_ * G_];          // transposed half pre-gate weights
__device__ float g_h[2 * BH];              // f32 (tf32-valued) recurrence state
__device__ unsigned g_bar;

// ---------------- helpers ---------------------------------------------------
__device__ __forceinline__ float f2tf32(float x) {
    uint32_t u;
    asm("cvt.rna.tf32.f32 %0, %1;" : "=r"(u) : "f"(x));
    return __uint_as_float(u);
}

__device__ __forceinline__ void mma_tf32(float* d, const uint32_t* a, const uint32_t* b) {
    asm volatile(
        "mma.sync.aligned.m16n8k8.row.col.f32.tf32.tf32.f32 "
        "{%0,%1,%2,%3}, {%4,%5,%6,%7}, {%8,%9}, {%0,%1,%2,%3};\n"
        : "+f"(d[0]), "+f"(d[1]), "+f"(d[2]), "+f"(d[3])
        : "r"(a[0]), "r"(a[1]), "r"(a[2]), "r"(a[3]), "r"(b[0]), "r"(b[1]));
}

__device__ __forceinline__ void mma_fp16(float* d, const uint32_t* a, const uint32_t* b) {
    asm volatile(
        "mma.sync.aligned.m16n8k16.row.col.f32.f16.f16.f32 "
        "{%0,%1,%2,%3}, {%4,%5,%6,%7}, {%8,%9}, {%0,%1,%2,%3};\n"
        : "+f"(d[0]), "+f"(d[1]), "+f"(d[2]), "+f"(d[3])
        : "r"(a[0]), "r"(a[1]), "r"(a[2]), "r"(a[3]), "r"(b[0]), "r"(b[1]));
}

__device__ __forceinline__ float sigm(float x) { return 1.f / (1.f + expf(-x)); }

__device__ __forceinline__ unsigned ld_acq(const unsigned* p) {
    unsigned v;
    asm volatile("ld.acquire.gpu.u32 %0, [%1];" : "=r"(v) : "l"(p) : "memory");
    return v;
}

__device__ __forceinline__ void cp16(uint32_t dst, const void* src) {
    asm volatile("cp.async.cg.shared.global [%0], [%1], 16;" :: "r"(dst), "l"(src));
}
#define CP_COMMIT() asm volatile("cp.async.commit_group;")
#define CP_WAIT(N)  asm volatile("cp.async.wait_group %0;" :: "n"(N))

// ---------------- embedding gather (-> half) --------------------------------
__global__ void gather_kernel(const int* __restrict__ data,
                              const float* __restrict__ emb,
                              __half* __restrict__ X0h) {
    int tb = blockIdx.x;
    int idx = data[tb];
    const float4* src = reinterpret_cast<const float4*>(emb + (size_t)idx * EMB_);
    float4 v = src[threadIdx.x];
    __half2 h0 = __floats2half2_rn(v.x, v.y);
    __half2 h1 = __floats2half2_rn(v.z, v.w);
    uint2 pk = make_uint2(*reinterpret_cast<uint32_t*>(&h0),
                          *reinterpret_cast<uint32_t*>(&h1));
    reinterpret_cast<uint2*>(X0h + (size_t)tb * EMB_)[threadIdx.x] = pk;
}

// ---------------- transpose + f32->half: out[n][k] = half(in[k][n]) ---------
__global__ void trans_half(const float* __restrict__ in, __half* __restrict__ outp,
                           int Kdim, int Ndim) {
    __shared__ float t[32][33];
    int nb = blockIdx.x * 32, kb = blockIdx.y * 32;
    int x = threadIdx.x, y = threadIdx.y;   // block (32, 8)
#pragma unroll
    for (int i = 0; i < 32; i += 8)
        t[y + i][x] = in[(size_t)(kb + y + i) * Ndim + nb + x];
    __syncthreads();
#pragma unroll
    for (int i = 0; i < 32; i += 8)
        outp[(size_t)(nb + y + i) * Kdim + kb + x] = __float2half(t[x][y + i]);
}

// ---------------- state zero + barrier reset --------------------------------
__global__ void zero_state(float* __restrict__ h, unsigned* __restrict__ bar) {
    int i = blockIdx.x * blockDim.x + threadIdx.x;
    if (i < 2 * BH) h[i] = 0.f;
    if (i == 0) *bar = 0u;
}

// ---------------- fp16 pipelined GEMM: C = A @ Bt^T + bias ------------------
// A [M, lda] half row-major, Bt [N, K] half row-major (pre-transposed).
// 128x256 block tile, 256 threads (8 warps, 64x64 warp tiles),
// 3-stage cp.async pipeline (K-stage 64), supertile swizzle. C f32.
__global__ __launch_bounds__(256, 1) void gemm_fp16_pipe(
    const __half* __restrict__ A, int lda,
    const __half* __restrict__ Bt,
    const float* __restrict__ bias,
    float* __restrict__ C, int ldc, int K, int ntiles, int mtiles)
{
    extern __shared__ char smc[];

    int lin = blockIdx.x;
    int n_t, m_t;
    {
        int full = ntiles / GSW;
        int blocksFull = full * GSW * mtiles;
        if (lin < blocksFull) {
            int sid = lin / (GSW * mtiles);
            int r = lin - sid * (GSW * mtiles);
            n_t = sid * GSW + (r % GSW);
            m_t = r / GSW;
        } else {
            int r = lin - blocksFull;
            int wd = ntiles - full * GSW;
            n_t = full * GSW + (r % wd);
            m_t = r / wd;
        }
    }
    const int n0 = n_t * GBN;
    const int m0 = m_t * GBM;

    const int tid = threadIdx.x;
    const int lane = tid & 31, warp = tid >> 5;
    const int wm = (warp & 1) * 64;       // 2 M groups
    const int wn = (warp >> 1) * 64;      // 4 N groups
    const int g = lane >> 2, tig = lane & 3;

    const uint32_t sm_u32 = (uint32_t)__cvta_generic_to_shared(smc);

    float acc[4][8][4];
#pragma unroll
    for (int i = 0; i < 4; i++)
#pragma unroll
        for (int j = 0; j < 8; j++)
#pragma unroll
            for (int r = 0; r < 4; r++) acc[i][j][r] = 0.f;

    auto issue_stage = [&](int kb, int s) {
        int k0 = kb * GBK;
        uint32_t aS = sm_u32 + (uint32_t)(s * STAGE_H) * 2;
        uint32_t bS = aS + A_STAGE_H * 2;
#pragma unroll
        for (int i = 0; i < 4; i++) {               // A: 128 rows x 64 halves
            int idx = tid + i * 256;
            int row = idx >> 3, kq = (idx & 7) << 3;
            cp16(aS + (uint32_t)(row * ASTH + kq) * 2,
                 A + (size_t)(m0 + row) * lda + k0 + kq);
        }
#pragma unroll
        for (int i = 0; i < 8; i++) {               // B: 256 rows x 64 halves
            int idx = tid + i * 256;
            int row = idx >> 3, kq = (idx & 7) << 3;
            cp16(bS + (uint32_t)(row * BSTH + kq) * 2,
                 Bt + (size_t)(n0 + row) * K + k0 + kq);
        }
        CP_COMMIT();
    };
    auto compute_stage = [&](int s) {
        const __half* aS = reinterpret_cast<const __half*>(smc) + s * STAGE_H;
        const __half* bS = aS + A_STAGE_H;
#pragma unroll
        for (int it = 0; it < 4; it++) {
            const int ks = it * 16;
            uint32_t af[4][4];
#pragma unroll
            for (int mt = 0; mt < 4; mt++) {
                int mb = wm + mt * 16 + g;
                af[mt][0] = *reinterpret_cast<const uint32_t*>(aS + mb * ASTH + ks + 2 * tig);
                af[mt][1] = *reinterpret_cast<const uint32_t*>(aS + (mb + 8) * ASTH + ks + 2 * tig);
                af[mt][2] = *reinterpret_cast<const uint32_t*>(aS + mb * ASTH + ks + 2 * tig + 8);
                af[mt][3] = *reinterpret_cast<const uint32_t*>(aS + (mb + 8) * ASTH + ks + 2 * tig + 8);
            }
#pragma unroll
            for (int nt = 0; nt < 8; nt++) {
                int nb = wn + nt * 8 + g;
                uint32_t bf[2];
                bf[0] = *reinterpret_cast<const uint32_t*>(bS + nb * BSTH + ks + 2 * tig);
                bf[1] = *reinterpret_cast<const uint32_t*>(bS + nb * BSTH + ks + 2 * tig + 8);
#pragma unroll
                for (int mt = 0; mt < 4; mt++)
                    mma_fp16(acc[mt][nt], af[mt], bf);
            }
        }
    };

    const int nk = K >> 6;
    issue_stage(0, 0);
    issue_stage(1, 1);
    int s = 0;
    for (int kb = 0; kb < nk; kb++) {
        if (kb < nk - 1) { CP_WAIT(1); } else { CP_WAIT(0); }
        __syncthreads();
        compute_stage(s);
        if (kb + 2 < nk) {
            int nb = s + 2; if (nb >= 3) nb -= 3;
            issue_stage(kb + 2, nb);
        }
        s = s + 1; if (s == 3) s = 0;
    }

#pragma unroll
    for (int mt = 0; mt < 4; mt++) {
        int m = m0 + wm + mt * 16 + g;
#pragma unroll
        for (int nt = 0; nt < 8; nt++) {
            int n = n0 + wn + nt * 8 + 2 * tig;
            float bx = bias[n], by = bias[n + 1];
            float2 v0 = make_float2(acc[mt][nt][0] + bx, acc[mt][nt][1] + by);
            float2 v1 = make_float2(acc[mt][nt][2] + bx, acc[mt][nt][3] + by);
            *reinterpret_cast<float2*>(C + (size_t)m * ldc + n) = v0;
            *reinterpret_cast<float2*>(C + (size_t)(m + 8) * ldc + n) = v1;
        }
    }
}

// ---------------- persistent LSTM layer (central barrier; measured best) ----
#define WHS_BYTES 131072
#define HB_BYTES  (NW * 2 * CBYTES)
#define SMEM_PERSIST (WHS_BYTES + HB_BYTES)

__global__ __launch_bounds__(256, 1) void lstm_persist(
    const float* __restrict__ Xg,
    const float* __restrict__ Wh,
    float* __restrict__ hbuf,
    __half* __restrict__ Hout,         // half for next layer's fp16 GEMM
    unsigned* __restrict__ bar)
{
    extern __shared__ char smx[];
    float2* Whs = reinterpret_cast<float2*>(smx);
    float*  scr = reinterpret_cast<float*>(smx + WHS_BYTES);

    const int tid = threadIdx.x;
    const int lane = tid & 31, warp = tid >> 5;
    const int g = lane >> 2, tig = lane & 3;
    const int u0 = blockIdx.x * UPB;

    const uint32_t smem_u32 = (uint32_t)__cvta_generic_to_shared(smx);
    const uint32_t hb_u32 = smem_u32 + WHS_BYTES + warp * 2 * CBYTES;
    float* hb_gen = reinterpret_cast<float*>(smx + WHS_BYTES + warp * 2 * CBYTES);

    for (int ko = warp; ko < 128; ko += NW) {
#pragma unroll
        for (int nt = 0; nt < 4; nt++) {
            int col = nt * HID_ + u0 + g;
            float b0 = Wh[(size_t)(ko * 8 + tig) * G_ + col];
            float b1 = Wh[(size_t)(ko * 8 + tig + 4) * G_ + col];
            Whs[(ko * 4 + nt) * 32 + lane] = make_float2(f2tf32(b0), f2tf32(b1));
        }
    }
    __syncthreads();

    const int pm = tid >> 3, pul = tid & 7;
    const int pmt = pm >> 4;
    const int pgg = (pm & 15) & 7, phi = (pm & 15) >> 3;
    const int pr = phi * 2 + (pul & 1);
    const int pln = pgg * 4 + (pul >> 1);
    const size_t xgbase = (size_t)pm * G_ + u0 + pul;

    const int r8 = lane >> 3, kk = lane & 7;
    const int kw = warp * 128;

    float creg = 0.f;
    float xr[4];
#pragma unroll
    for (int s = 0; s < 4; s++) xr[s] = Xg[xgbase + s * HID_];

    for (int t = 0; t < T_; t++) {
        const float* hin = hbuf + (t & 1) * BH;
        float* hnx = hbuf + ((t + 1) & 1) * BH;

        float acc[2][4][4];
#pragma unroll
        for (int mt = 0; mt < 2; mt++)
#pragma unroll
            for (int nt = 0; nt < 4; nt++)
#pragma unroll
                for (int r = 0; r < 4; r++) acc[mt][nt][r] = 0.f;

        auto cp_chunk = [&](int c, int b) {
            const int kbase = kw + c * CHK;
            const uint32_t dbase = hb_u32 + b * CBYTES + (kk * 4) * 4;
            const float* sbase = hin + r8 * HID_ + kbase + kk * 4;
#pragma unroll
            for (int p = 0; p < 8; p++) {
                int row4 = p * 4;
                cp16(dbase + (uint32_t)((row4 + r8) * CSTRIDE) * 4,
                     sbase + (size_t)row4 * HID_);
            }
            CP_COMMIT();
        };
        auto compute_chunk = [&](int c, int b) {
            const float* buf = hb_gen + b * (CBYTES / 4);
#pragma unroll
            for (int k8 = 0; k8 < 4; k8++) {
                int ko = warp * 16 + c * 4 + k8;
                int kA = k8 * 8 + tig;
                uint32_t af[2][4];
#pragma unroll
                for (int mt = 0; mt < 2; mt++) {
                    int mb = mt * 16;
                    af[mt][0] = __float_as_uint(buf[(mb + g) * CSTRIDE + kA]);
                    af[mt][1] = __float_as_uint(buf[(mb + g + 8) * CSTRIDE + kA]);
                    af[mt][2] = __float_as_uint(buf[(mb + g) * CSTRIDE + kA + 4]);
                    af[mt][3] = __float_as_uint(buf[(mb + g + 8) * CSTRIDE + kA + 4]);
                }
#pragma unroll
                for (int nt = 0; nt < 4; nt++) {
                    float2 bb = Whs[(ko * 4 + nt) * 32 + lane];
                    uint32_t bf[2] = {__float_as_uint(bb.x), __float_as_uint(bb.y)};
                    mma_tf32(acc[0][nt], af[0], bf);
                    mma_tf32(acc[1][nt], af[1], bf);
                }
            }
        };

        cp_chunk(0, 0);
        cp_chunk(1, 1);
        CP_WAIT(1); __syncwarp();
        compute_chunk(0, 0);
        cp_chunk(2, 0);
        CP_WAIT(1); __syncwarp();
        compute_chunk(1, 1);
        cp_chunk(3, 1);
        CP_WAIT(1); __syncwarp();
        compute_chunk(2, 0);
        CP_WAIT(0); __syncwarp();
        compute_chunk(3, 1);

        __syncthreads();
#pragma unroll
        for (int mt = 0; mt < 2; mt++)
#pragma unroll
            for (int nt = 0; nt < 4; nt++)
#pragma unroll
                for (int r = 0; r < 4; r++) {
                    int ridx = mt * 16 + nt * 4 + r;
                    scr[((warp * 32 + ridx) << 5) + lane] = acc[mt][nt][r];
                }
        __syncthreads();

        float hh;
        {
            float gv[4];
#pragma unroll
            for (int s = 0; s < 4; s++) {
                int ridx = pmt * 16 + s * 4 + pr;
                float v = 0.f;
#pragma unroll
                for (int w = 0; w < NW; w++)
                    v += scr[((w * 32 + ridx) << 5) + pln];
                gv[s] = v + xr[s];
            }
            float cc = creg;
            cc = sigm(gv[2] + 1.f) * cc + sigm(gv[0]) * tanhf(gv[1]);
            hh = sigm(gv[3]) * tanhf(cc);
            creg = cc;
            hnx[pm * HID_ + u0 + pul] = f2tf32(hh);
        }

        if (t < T_ - 1) {
            __syncthreads();
            if (tid == 0) {
                __threadfence();
                atomicAdd(bar, 1u);
            }
            Hout[((size_t)(t * B_ + pm)) * HID_ + u0 + pul] = __float2half(hh);
            const size_t xb = xgbase + (size_t)(t + 1) * B_ * G_;
#pragma unroll
            for (int s = 0; s < 4; s++) xr[s] = Xg[xb + s * HID_];
            if (tid == 0) {
                unsigned target = (unsigned)(t + 1) * NBLK;
                while (ld_acq(bar) < target) { }
            }
            __syncthreads();
        } else {
            Hout[((size_t)(t * B_ + pm)) * HID_ + u0 + pul] = __float2half(hh);
        }
    }
}

// ---------------- launch ----------------------------------------------------
extern "C" void kernel_launch(void* const* d_in, const int* in_sizes, int n_in,
                              void* d_out, int out_size) {
    const int*   data = (const int*)d_in[0];
    const float* emb  = (const float*)d_in[2];
    const float* W0   = (const float*)d_in[3];
    const float* b0   = (const float*)d_in[4];
    const float* W1   = (const float*)d_in[5];
    const float* b1   = (const float*)d_in[6];
    const float* W2   = (const float*)d_in[7];
    const float* b2   = (const float*)d_in[8];
    const float* Wd   = (const float*)d_in[9];
    const float* bd   = (const float*)d_in[10];
    float* out = (float*)d_out;
    (void)in_sizes; (void)n_in; (void)out_size;

    float *X0, *HA, *HB, *Xg, *Wr, *h;
    unsigned* bar;
    cudaGetSymbolAddress((void**)&X0, g_X0);
    cudaGetSymbolAddress((void**)&HA, g_HA);
    cudaGetSymbolAddress((void**)&HB, g_HB);
    cudaGetSymbolAddress((void**)&Xg, g_Xg);
    cudaGetSymbolAddress((void**)&Wr, g_Wr);
    cudaGetSymbolAddress((void**)&h,  g_h);
    cudaGetSymbolAddress((void**)&bar, g_bar);

    __half* X0h = reinterpret_cast<__half*>(X0);
    __half* HAh = reinterpret_cast<__half*>(HA);
    __half* HBh = reinterpret_cast<__half*>(HB);
    __half* Wrh = reinterpret_cast<__half*>(Wr);
    __half* WdTh = reinterpret_cast<__half*>(Xg);

    cudaFuncSetAttribute(lstm_persist, cudaFuncAttributeMaxDynamicSharedMemorySize,
                         SMEM_PERSIST);
    cudaFuncSetAttribute(gemm_fp16_pipe, cudaFuncAttributeMaxDynamicSharedMemorySize,
                         GEMM_SMEM);

    gather_kernel<<<TB_, 128>>>(data, emb, X0h);

    const int zgrid = (2 * BH + 255) / 256;
    const int MT = TB_ / GBM;          // 64

    // layer 0 (Din = 512)
    trans_half<<<dim3(G_ / 32, EMB_ / 32), dim3(32, 8)>>>(W0, Wrh, EMB_, G_);
    zero_state<<<zgrid, 256>>>(h, bar);
    gemm_fp16_pipe<<<MT * (G_ / GBN), 256, GEMM_SMEM>>>(
        X0h, EMB_, Wrh, b0, Xg, G_, EMB_, G_ / GBN, MT);
    lstm_persist<<<NBLK, 256, SMEM_PERSIST>>>(Xg, W0 + (size_t)EMB_ * G_, h, HAh, bar);

    // layer 1
    trans_half<<<dim3(G_ / 32, HID_ / 32), dim3(32, 8)>>>(W1, Wrh, HID_, G_);
    zero_state<<<zgrid, 256>>>(h, bar);
    gemm_fp16_pipe<<<MT * (G_ / GBN), 256, GEMM_SMEM>>>(
        HAh, HID_, Wrh, b1, Xg, G_, HID_, G_ / GBN, MT);
    lstm_persist<<<NBLK, 256, SMEM_PERSIST>>>(Xg, W1 + (size_t)HID_ * G_, h, HBh, bar);

    // layer 2
    trans_half<<<dim3(G_ / 32, HID_ / 32), dim3(32, 8)>>>(W2, Wrh, HID_, G_);
    zero_state<<<zgrid, 256>>>(h, bar);
    gemm_fp16_pipe<<<MT * (G_ / GBN), 256, GEMM_SMEM>>>(
        HBh, HID_, Wrh, b2, Xg, G_, HID_, G_ / GBN, MT);
    lstm_persist<<<NBLK, 256, SMEM_PERSIST>>>(Xg, W2 + (size_t)HID_ * G_, h, HAh, bar);

    // projection: Wd^T (half) into the now-dead Xg buffer, then fp16 GEMM
    trans_half<<<dim3(VOCAB_ / 32, HID_ / 32), dim3(32, 8)>>>(Wd, WdTh, HID_, VOCAB_);
    gemm_fp16_pipe<<<MT * (VOCAB_ / GBN), 256, GEMM_SMEM>>>(
        HAh, HID_, WdTh, bd, out, VOCAB_, HID_, VOCAB_ / GBN, MT);
}

// round 12
// speedup vs baseline: 1.8966x; 1.1254x over previous
#include <cuda_runtime.h>
#include <cuda_fp16.h>
#include <cstdint>
#include <math.h>

#define T_     256
#define B_     32
#define VOCAB_ 32000
#define EMB_   512
#define HID_   1024
#define G_     4096   // 4*HID
#define TB_    8192   // T_*B_
#define NBLK   128    // persistent blocks (1 per SM)
#define UPB    8      // hidden units per block (128*8 = 1024)
#define BH     (B_ * HID_)
#define NW     8      // warps per block in lstm_persist

// fp16 recurrence chunking: 32 m x 32 k halves per chunk, stride 40 halves
#define CSTH   40
#define CBH    (32 * CSTH * 2)        // 2560 B per chunk buffer

// fp16 pipelined GEMM config (K-stage = 64, 8 warps, 64x64 warp tiles)
#define GBM 128
#define GBN 256
#define GBK 64
#define ASTH 72
#define BSTH 72
#define A_STAGE_H (GBM * ASTH)
#define B_STAGE_H (GBN * BSTH)
#define STAGE_H (A_STAGE_H + B_STAGE_H)
#define GEMM_SMEM (3 * STAGE_H * 2)    // 165888 B
#define GSW 8

// ---------------- scratch (device globals; no allocations allowed) ----------
__device__ float g_X0[TB_ * EMB_];         // used as half[TB][EMB]
__device__ float g_HA[TB_ * HID_];         // used as half[TB][HID]
__device__ float g_HB[TB_ * HID_];         // used as half[TB][HID]
__device__ float g_Xg[(size_t)TB_ * G_];   // f32 gate priors; later WdT half
__device__ float g_Wr[HID_ * G_];          // transposed half pre-gate weights
__device__ float g_h[2 * BH];              // used as half[2][BH]
__device__ unsigned g_bar;

// ---------------- helpers ---------------------------------------------------
__device__ __forceinline__ void mma_fp16(float* d, const uint32_t* a, const uint32_t* b) {
    asm volatile(
        "mma.sync.aligned.m16n8k16.row.col.f32.f16.f16.f32 "
        "{%0,%1,%2,%3}, {%4,%5,%6,%7}, {%8,%9}, {%0,%1,%2,%3};\n"
        : "+f"(d[0]), "+f"(d[1]), "+f"(d[2]), "+f"(d[3])
        : "r"(a[0]), "r"(a[1]), "r"(a[2]), "r"(a[3]), "r"(b[0]), "r"(b[1]));
}

__device__ __forceinline__ float sigm(float x) { return 1.f / (1.f + expf(-x)); }

__device__ __forceinline__ unsigned ld_acq(const unsigned* p) {
    unsigned v;
    asm volatile("ld.acquire.gpu.u32 %0, [%1];" : "=r"(v) : "l"(p) : "memory");
    return v;
}

__device__ __forceinline__ void cp16(uint32_t dst, const void* src) {
    asm volatile("cp.async.cg.shared.global [%0], [%1], 16;" :: "r"(dst), "l"(src));
}
#define CP_COMMIT() asm volatile("cp.async.commit_group;")
#define CP_WAIT(N)  asm volatile("cp.async.wait_group %0;" :: "n"(N))

__device__ __forceinline__ uint32_t pack_half2(float a, float b) {
    __half2 h = __floats2half2_rn(a, b);
    return *reinterpret_cast<uint32_t*>(&h);
}

// ---------------- embedding gather (-> half) --------------------------------
__global__ void gather_kernel(const int* __restrict__ data,
                              const float* __restrict__ emb,
                              __half* __restrict__ X0h) {
    int tb = blockIdx.x;
    int idx = data[tb];
    const float4* src = reinterpret_cast<const float4*>(emb + (size_t)idx * EMB_);
    float4 v = src[threadIdx.x];
    uint2 pk = make_uint2(pack_half2(v.x, v.y), pack_half2(v.z, v.w));
    reinterpret_cast<uint2*>(X0h + (size_t)tb * EMB_)[threadIdx.x] = pk;
}

// ---------------- transpose + f32->half: out[n][k] = half(in[k][n]) ---------
__global__ void trans_half(const float* __restrict__ in, __half* __restrict__ outp,
                           int Kdim, int Ndim) {
    __shared__ float t[32][33];
    int nb = blockIdx.x * 32, kb = blockIdx.y * 32;
    int x = threadIdx.x, y = threadIdx.y;   // block (32, 8)
#pragma unroll
    for (int i = 0; i < 32; i += 8)
        t[y + i][x] = in[(size_t)(kb + y + i) * Ndim + nb + x];
    __syncthreads();
#pragma unroll
    for (int i = 0; i < 32; i += 8)
        outp[(size_t)(nb + y + i) * Kdim + kb + x] = __float2half(t[x][y + i]);
}

// ---------------- state zero + barrier reset --------------------------------
__global__ void zero_state(float* __restrict__ h, unsigned* __restrict__ bar) {
    int i = blockIdx.x * blockDim.x + threadIdx.x;
    if (i < 2 * BH) h[i] = 0.f;
    if (i == 0) *bar = 0u;
}

// ---------------- fp16 pipelined GEMM: C = A @ Bt^T + bias ------------------
__global__ __launch_bounds__(256, 1) void gemm_fp16_pipe(
    const __half* __restrict__ A, int lda,
    const __half* __restrict__ Bt,
    const float* __restrict__ bias,
    float* __restrict__ C, int ldc, int K, int ntiles, int mtiles)
{
    extern __shared__ char smc[];

    int lin = blockIdx.x;
    int n_t, m_t;
    {
        int full = ntiles / GSW;
        int blocksFull = full * GSW * mtiles;
        if (lin < blocksFull) {
            int sid = lin / (GSW * mtiles);
            int r = lin - sid * (GSW * mtiles);
            n_t = sid * GSW + (r % GSW);
            m_t = r / GSW;
        } else {
            int r = lin - blocksFull;
            int wd = ntiles - full * GSW;
            n_t = full * GSW + (r % wd);
            m_t = r / wd;
        }
    }
    const int n0 = n_t * GBN;
    const int m0 = m_t * GBM;

    const int tid = threadIdx.x;
    const int lane = tid & 31, warp = tid >> 5;
    const int wm = (warp & 1) * 64;
    const int wn = (warp >> 1) * 64;
    const int g = lane >> 2, tig = lane & 3;

    const uint32_t sm_u32 = (uint32_t)__cvta_generic_to_shared(smc);

    float acc[4][8][4];
#pragma unroll
    for (int i = 0; i < 4; i++)
#pragma unroll
        for (int j = 0; j < 8; j++)
#pragma unroll
            for (int r = 0; r < 4; r++) acc[i][j][r] = 0.f;

    auto issue_stage = [&](int kb, int s) {
        int k0 = kb * GBK;
        uint32_t aS = sm_u32 + (uint32_t)(s * STAGE_H) * 2;
        uint32_t bS = aS + A_STAGE_H * 2;
#pragma unroll
        for (int i = 0; i < 4; i++) {
            int idx = tid + i * 256;
            int row = idx >> 3, kq = (idx & 7) << 3;
            cp16(aS + (uint32_t)(row * ASTH + kq) * 2,
                 A + (size_t)(m0 + row) * lda + k0 + kq);
        }
#pragma unroll
        for (int i = 0; i < 8; i++) {
            int idx = tid + i * 256;
            int row = idx >> 3, kq = (idx & 7) << 3;
            cp16(bS + (uint32_t)(row * BSTH + kq) * 2,
                 Bt + (size_t)(n0 + row) * K + k0 + kq);
        }
        CP_COMMIT();
    };
    auto compute_stage = [&](int s) {
        const __half* aS = reinterpret_cast<const __half*>(smc) + s * STAGE_H;
        const __half* bS = aS + A_STAGE_H;
#pragma unroll
        for (int it = 0; it < 4; it++) {
            const int ks = it * 16;
            uint32_t af[4][4];
#pragma unroll
            for (int mt = 0; mt < 4; mt++) {
                int mb = wm + mt * 16 + g;
                af[mt][0] = *reinterpret_cast<const uint32_t*>(aS + mb * ASTH + ks + 2 * tig);
                af[mt][1] = *reinterpret_cast<const uint32_t*>(aS + (mb + 8) * ASTH + ks + 2 * tig);
                af[mt][2] = *reinterpret_cast<const uint32_t*>(aS + mb * ASTH + ks + 2 * tig + 8);
                af[mt][3] = *reinterpret_cast<const uint32_t*>(aS + (mb + 8) * ASTH + ks + 2 * tig + 8);
            }
#pragma unroll
            for (int nt = 0; nt < 8; nt++) {
                int nb = wn + nt * 8 + g;
                uint32_t bf[2];
                bf[0] = *reinterpret_cast<const uint32_t*>(bS + nb * BSTH + ks + 2 * tig);
                bf[1] = *reinterpret_cast<const uint32_t*>(bS + nb * BSTH + ks + 2 * tig + 8);
#pragma unroll
                for (int mt = 0; mt < 4; mt++)
                    mma_fp16(acc[mt][nt], af[mt], bf);
            }
        }
    };

    const int nk = K >> 6;
    issue_stage(0, 0);
    issue_stage(1, 1);
    int s = 0;
    for (int kb = 0; kb < nk; kb++) {
        if (kb < nk - 1) { CP_WAIT(1); } else { CP_WAIT(0); }
        __syncthreads();
        compute_stage(s);
        if (kb + 2 < nk) {
            int nb = s + 2; if (nb >= 3) nb -= 3;
            issue_stage(kb + 2, nb);
        }
        s = s + 1; if (s == 3) s = 0;
    }

#pragma unroll
    for (int mt = 0; mt < 4; mt++) {
        int m = m0 + wm + mt * 16 + g;
#pragma unroll
        for (int nt = 0; nt < 8; nt++) {
            int n = n0 + wn + nt * 8 + 2 * tig;
            float bx = bias[n], by = bias[n + 1];
            float2 v0 = make_float2(acc[mt][nt][0] + bx, acc[mt][nt][1] + by);
            float2 v1 = make_float2(acc[mt][nt][2] + bx, acc[mt][nt][3] + by);
            *reinterpret_cast<float2*>(C + (size_t)m * ldc + n) = v0;
            *reinterpret_cast<float2*>(C + (size_t)(m + 8) * ldc + n) = v1;
        }
    }
}

// ---------------- persistent LSTM layer: fp16 mma, fp16 h -------------------
// 128 blocks x 256 threads (8 warps). Block owns 8 units (32 gate cols).
// Wh slice in SMEM as m16n8k16 B-fragments (half): 64 KB, resident 256 steps.
// h stored as half; per-step broadcast traffic halves vs f32.
// K split 8 ways (128/warp = 8 k16-groups, 4 chunks of 32 k, 2 bufs).
#define WHS_BYTES 65536
#define HB_BYTES  (NW * 2 * CBH)       // 40960
#define SMEM_PERSIST (WHS_BYTES + HB_BYTES)

__global__ __launch_bounds__(256, 1) void lstm_persist(
    const float* __restrict__ Xg,
    const float* __restrict__ Wh,      // f32 [HID_][G_] (rows Din..Din+H of W)
    __half* __restrict__ hbuf,         // half [2][BH] (zeroed)
    __half* __restrict__ Hout,         // half for next layer's fp16 GEMM
    unsigned* __restrict__ bar)
{
    extern __shared__ char smx[];
    uint2* Whs = reinterpret_cast<uint2*>(smx);          // [64 ko][4 nt][32 lane]
    float* scr = reinterpret_cast<float*>(smx + WHS_BYTES);  // alias of chunk bufs

    const int tid = threadIdx.x;
    const int lane = tid & 31, warp = tid >> 5;
    const int g = lane >> 2, tig = lane & 3;
    const int u0 = blockIdx.x * UPB;

    const uint32_t smem_u32 = (uint32_t)__cvta_generic_to_shared(smx);
    const uint32_t hb_u32 = smem_u32 + WHS_BYTES + warp * 2 * CBH;
    const uint32_t* hb_gen =
        reinterpret_cast<const uint32_t*>(smx + WHS_BYTES + warp * 2 * CBH);

    // ---- one-time: Wh slice -> half B-fragments (m16n8k16) ----
    for (int ko = warp; ko < 64; ko += NW) {
        int k0 = ko * 16;
#pragma unroll
        for (int nt = 0; nt < 4; nt++) {
            int col = nt * HID_ + u0 + g;
            uint32_t r0 = pack_half2(Wh[(size_t)(k0 + 2 * tig) * G_ + col],
                                     Wh[(size_t)(k0 + 2 * tig + 1) * G_ + col]);
            uint32_t r1 = pack_half2(Wh[(size_t)(k0 + 2 * tig + 8) * G_ + col],
                                     Wh[(size_t)(k0 + 2 * tig + 9) * G_ + col]);
            Whs[(ko * 4 + nt) * 32 + lane] = make_uint2(r0, r1);
        }
    }
    __syncthreads();

    // pointwise mapping (identical output layout to previous rounds)
    const int pm = tid >> 3, pul = tid & 7;
    const int pmt = pm >> 4;
    const int pgg = (pm & 15) & 7, phi = (pm & 15) >> 3;
    const int pr = phi * 2 + (pul & 1);
    const int pln = pgg * 4 + (pul >> 1);
    const size_t xgbase = (size_t)pm * G_ + u0 + pul;

    const int kw = warp * 128;         // this warp's K base (halves)

    float creg = 0.f;
    float xr[4];
#pragma unroll
    for (int s = 0; s < 4; s++) xr[s] = Xg[xgbase + s * HID_];

    for (int t = 0; t < T_; t++) {
        const __half* hin = hbuf + (t & 1) * BH;
        __half* hnx = hbuf + ((t + 1) & 1) * BH;

        float acc[2][4][4];
#pragma unroll
        for (int mt = 0; mt < 2; mt++)
#pragma unroll
            for (int nt = 0; nt < 4; nt++)
#pragma unroll
                for (int r = 0; r < 4; r++) acc[mt][nt][r] = 0.f;

        // chunk = 32 m x 32 k halves; 128 cp16 per chunk, 4 per lane
        auto cp_chunk = [&](int c, int b) {
            const int kbase = kw + c * 32;
            const uint32_t dbase = hb_u32 + b * CBH;
#pragma unroll
            for (int i = 0; i < 4; i++) {
                int idx = i * 32 + lane;
                int row = idx >> 2, q = idx & 3;
                cp16(dbase + (uint32_t)(row * (CSTH * 2) + q * 16),
                     hin + (size_t)row * HID_ + kbase + q * 8);
            }
            CP_COMMIT();
        };
        auto compute_chunk = [&](int c, int b) {
            const uint32_t* buf = hb_gen + b * (CBH / 4);
#pragma unroll
            for (int ks16 = 0; ks16 < 2; ks16++) {
                int ko = warp * 8 + c * 2 + ks16;
                uint32_t af[2][4];
#pragma unroll
                for (int mt = 0; mt < 2; mt++) {
                    int mb = mt * 16;
                    int base0 = (mb + g) * (CSTH / 2) + ks16 * 8 + tig;
                    int base1 = (mb + g + 8) * (CSTH / 2) + ks16 * 8 + tig;
                    af[mt][0] = buf[base0];
                    af[mt][1] = buf[base1];
                    af[mt][2] = buf[base0 + 4];
                    af[mt][3] = buf[base1 + 4];
                }
#pragma unroll
                for (int nt = 0; nt < 4; nt++) {
                    uint2 bb = Whs[(ko * 4 + nt) * 32 + lane];
                    uint32_t bf[2] = {bb.x, bb.y};
                    mma_fp16(acc[0][nt], af[0], bf);
                    mma_fp16(acc[1][nt], af[1], bf);
                }
            }
        };

        cp_chunk(0, 0);
        cp_chunk(1, 1);
        CP_WAIT(1); __syncwarp();
        compute_chunk(0, 0);
        cp_chunk(2, 0);
        CP_WAIT(1); __syncwarp();
        compute_chunk(1, 1);
        cp_chunk(3, 1);
        CP_WAIT(1); __syncwarp();
        compute_chunk(2, 0);
        CP_WAIT(0); __syncwarp();
        compute_chunk(3, 1);

        // ---- reduce K-partials across 8 warps (scr aliases chunk bufs) ----
        __syncthreads();
#pragma unroll
        for (int mt = 0; mt < 2; mt++)
#pragma unroll
            for (int nt = 0; nt < 4; nt++)
#pragma unroll
                for (int r = 0; r < 4; r++) {
                    int ridx = mt * 16 + nt * 4 + r;
                    scr[((warp * 32 + ridx) << 5) + lane] = acc[mt][nt][r];
                }
        __syncthreads();

        // ---- pointwise: one (batch, unit) pair per thread ----
        float hh;
        {
            float gv[4];
#pragma unroll
            for (int s = 0; s < 4; s++) {
                int ridx = pmt * 16 + s * 4 + pr;
                float v = 0.f;
#pragma unroll
                for (int w = 0; w < NW; w++)
                    v += scr[((w * 32 + ridx) << 5) + pln];
                gv[s] = v + xr[s];
            }
            float cc = creg;
            cc = sigm(gv[2] + 1.f) * cc + sigm(gv[0]) * tanhf(gv[1]);
            hh = sigm(gv[3]) * tanhf(cc);
            creg = cc;
            hnx[pm * HID_ + u0 + pul] = __float2half(hh);
        }

        if (t < T_ - 1) {
            __syncthreads();
            if (tid == 0) {
                __threadfence();
                atomicAdd(bar, 1u);
            }
            Hout[((size_t)(t * B_ + pm)) * HID_ + u0 + pul] = __float2half(hh);
            const size_t xb = xgbase + (size_t)(t + 1) * B_ * G_;
#pragma unroll
            for (int s = 0; s < 4; s++) xr[s] = Xg[xb + s * HID_];
            if (tid == 0) {
                unsigned target = (unsigned)(t + 1) * NBLK;
                while (ld_acq(bar) < target) { }
            }
            __syncthreads();
        } else {
            Hout[((size_t)(t * B_ + pm)) * HID_ + u0 + pul] = __float2half(hh);
        }
    }
}

// ---------------- launch ----------------------------------------------------
extern "C" void kernel_launch(void* const* d_in, const int* in_sizes, int n_in,
                              void* d_out, int out_size) {
    const int*   data = (const int*)d_in[0];
    const float* emb  = (const float*)d_in[2];
    const float* W0   = (const float*)d_in[3];
    const float* b0   = (const float*)d_in[4];
    const float* W1   = (const float*)d_in[5];
    const float* b1   = (const float*)d_in[6];
    const float* W2   = (const float*)d_in[7];
    const float* b2   = (const float*)d_in[8];
    const float* Wd   = (const float*)d_in[9];
    const float* bd   = (const float*)d_in[10];
    float* out = (float*)d_out;
    (void)in_sizes; (void)n_in; (void)out_size;

    float *X0, *HA, *HB, *Xg, *Wr, *h;
    unsigned* bar;
    cudaGetSymbolAddress((void**)&X0, g_X0);
    cudaGetSymbolAddress((void**)&HA, g_HA);
    cudaGetSymbolAddress((void**)&HB, g_HB);
    cudaGetSymbolAddress((void**)&Xg, g_Xg);
    cudaGetSymbolAddress((void**)&Wr, g_Wr);
    cudaGetSymbolAddress((void**)&h,  g_h);
    cudaGetSymbolAddress((void**)&bar, g_bar);

    __half* X0h = reinterpret_cast<__half*>(X0);
    __half* HAh = reinterpret_cast<__half*>(HA);
    __half* HBh = reinterpret_cast<__half*>(HB);
    __half* Wrh = reinterpret_cast<__half*>(Wr);
    __half* WdTh = reinterpret_cast<__half*>(Xg);
    __half* hh_ = reinterpret_cast<__half*>(h);

    cudaFuncSetAttribute(lstm_persist, cudaFuncAttributeMaxDynamicSharedMemorySize,
                         SMEM_PERSIST);
    cudaFuncSetAttribute(gemm_fp16_pipe, cudaFuncAttributeMaxDynamicSharedMemorySize,
                         GEMM_SMEM);

    gather_kernel<<<TB_, 128>>>(data, emb, X0h);

    const int zgrid = (2 * BH + 255) / 256;
    const int MT = TB_ / GBM;          // 64

    // layer 0 (Din = 512)
    trans_half<<<dim3(G_ / 32, EMB_ / 32), dim3(32, 8)>>>(W0, Wrh, EMB_, G_);
    zero_state<<<zgrid, 256>>>(h, bar);
    gemm_fp16_pipe<<<MT * (G_ / GBN), 256, GEMM_SMEM>>>(
        X0h, EMB_, Wrh, b0, Xg, G_, EMB_, G_ / GBN, MT);
    lstm_persist<<<NBLK, 256, SMEM_PERSIST>>>(Xg, W0 + (size_t)EMB_ * G_, hh_, HAh, bar);

    // layer 1
    trans_half<<<dim3(G_ / 32, HID_ / 32), dim3(32, 8)>>>(W1, Wrh, HID_, G_);
    zero_state<<<zgrid, 256>>>(h, bar);
    gemm_fp16_pipe<<<MT * (G_ / GBN), 256, GEMM_SMEM>>>(
        HAh, HID_, Wrh, b1, Xg, G_, HID_, G_ / GBN, MT);
    lstm_persist<<<NBLK, 256, SMEM_PERSIST>>>(Xg, W1 + (size_t)HID_ * G_, hh_, HBh, bar);

    // layer 2
    trans_half<<<dim3(G_ / 32, HID_ / 32), dim3(32, 8)>>>(W2, Wrh, HID_, G_);
    zero_state<<<zgrid, 256>>>(h, bar);
    gemm_fp16_pipe<<<MT * (G_ / GBN), 256, GEMM_SMEM>>>(
        HBh, HID_, Wrh, b2, Xg, G_, HID_, G_ / GBN, MT);
    lstm_persist<<<NBLK, 256, SMEM_PERSIST>>>(Xg, W2 + (size_t)HID_ * G_, hh_, HAh, bar);

    // projection: Wd^T (half) into the now-dead Xg buffer, then fp16 GEMM
    trans_half<<<dim3(VOCAB_ / 32, HID_ / 32), dim3(32, 8)>>>(Wd, WdTh, HID_, VOCAB_);
    gemm_fp16_pipe<<<MT * (VOCAB_ / GBN), 256, GEMM_SMEM>>>(
        HAh, HID_, WdTh, bd, out, VOCAB_, HID_, VOCAB_ / GBN, MT);
}

// round 13
// speedup vs baseline: 1.9013x; 1.0025x over previous
#include <cuda_runtime.h>
#include <cuda_fp16.h>
#include <cstdint>
#include <math.h>

#define T_     256
#define B_     32
#define VOCAB_ 32000
#define EMB_   512
#define HID_   1024
#define G_     4096   // 4*HID
#define TB_    8192   // T_*B_
#define NBLK   128    // persistent blocks (1 per SM)
#define UPB    8      // hidden units per block (128*8 = 1024)
#define BH     (B_ * HID_)
#define NW     8      // warps per block in lstm_persist
#define NCTR   8      // distributed barrier counters (16 blocks each)

// fp16 recurrence chunking: 32 m x 32 k halves per chunk, stride 40 halves
#define CSTH   40
#define CBH    (32 * CSTH * 2)        // 2560 B per chunk buffer

// fp16 pipelined GEMM config (K-stage = 64, 8 warps, 64x64 warp tiles)
#define GBM 128
#define GBN 256
#define GBK 64
#define ASTH 72
#define BSTH 72
#define A_STAGE_H (GBM * ASTH)
#define B_STAGE_H (GBN * BSTH)
#define STAGE_H (A_STAGE_H + B_STAGE_H)
#define GEMM_SMEM (3 * STAGE_H * 2)    // 165888 B
#define GSW 8

// ---------------- scratch (device globals; no allocations allowed) ----------
__device__ float g_X0[TB_ * EMB_];         // used as half[TB][EMB]
__device__ float g_HA[TB_ * HID_];         // used as half[TB][HID]
__device__ float g_HB[TB_ * HID_];         // used as half[TB][HID]
__device__ float g_Xg[(size_t)TB_ * G_];   // f32 gate priors; later WdT half
__device__ float g_Wr[HID_ * G_];          // transposed half pre-gate weights
__device__ float g_h[2 * BH];              // used as half[2][BH]
__device__ unsigned g_bar[NCTR * 32];      // 8 counters, 128 B apart

// ---------------- helpers ---------------------------------------------------
__device__ __forceinline__ void mma_fp16(float* d, const uint32_t* a, const uint32_t* b) {
    asm volatile(
        "mma.sync.aligned.m16n8k16.row.col.f32.f16.f16.f32 "
        "{%0,%1,%2,%3}, {%4,%5,%6,%7}, {%8,%9}, {%0,%1,%2,%3};\n"
        : "+f"(d[0]), "+f"(d[1]), "+f"(d[2]), "+f"(d[3])
        : "r"(a[0]), "r"(a[1]), "r"(a[2]), "r"(a[3]), "r"(b[0]), "r"(b[1]));
}

__device__ __forceinline__ float sigm(float x) { return 1.f / (1.f + expf(-x)); }

__device__ __forceinline__ unsigned ld_acq(const unsigned* p) {
    unsigned v;
    asm volatile("ld.acquire.gpu.u32 %0, [%1];" : "=r"(v) : "l"(p) : "memory");
    return v;
}

__device__ __forceinline__ void cp16(uint32_t dst, const void* src) {
    asm volatile("cp.async.cg.shared.global [%0], [%1], 16;" :: "r"(dst), "l"(src));
}
#define CP_COMMIT() asm volatile("cp.async.commit_group;")
#define CP_WAIT(N)  asm volatile("cp.async.wait_group %0;" :: "n"(N))

__device__ __forceinline__ uint32_t pack_half2(float a, float b) {
    __half2 h = __floats2half2_rn(a, b);
    return *reinterpret_cast<uint32_t*>(&h);
}

// ---------------- embedding gather (-> half) --------------------------------
__global__ void gather_kernel(const int* __restrict__ data,
                              const float* __restrict__ emb,
                              __half* __restrict__ X0h) {
    int tb = blockIdx.x;
    int idx = data[tb];
    const float4* src = reinterpret_cast<const float4*>(emb + (size_t)idx * EMB_);
    float4 v = src[threadIdx.x];
    uint2 pk = make_uint2(pack_half2(v.x, v.y), pack_half2(v.z, v.w));
    reinterpret_cast<uint2*>(X0h + (size_t)tb * EMB_)[threadIdx.x] = pk;
}

// ---------------- transpose + f32->half: out[n][k] = half(in[k][n]) ---------
__global__ void trans_half(const float* __restrict__ in, __half* __restrict__ outp,
                           int Kdim, int Ndim) {
    __shared__ float t[32][33];
    int nb = blockIdx.x * 32, kb = blockIdx.y * 32;
    int x = threadIdx.x, y = threadIdx.y;   // block (32, 8)
#pragma unroll
    for (int i = 0; i < 32; i += 8)
        t[y + i][x] = in[(size_t)(kb + y + i) * Ndim + nb + x];
    __syncthreads();
#pragma unroll
    for (int i = 0; i < 32; i += 8)
        outp[(size_t)(nb + y + i) * Kdim + kb + x] = __float2half(t[x][y + i]);
}

// ---------------- state zero + barrier reset --------------------------------
__global__ void zero_state(float* __restrict__ h, unsigned* __restrict__ bar) {
    int i = blockIdx.x * blockDim.x + threadIdx.x;
    if (i < 2 * BH) h[i] = 0.f;
    if (i < NCTR * 32) bar[i] = 0u;
}

// ---------------- fp16 pipelined GEMM: C = A @ Bt^T + bias ------------------
__global__ __launch_bounds__(256, 1) void gemm_fp16_pipe(
    const __half* __restrict__ A, int lda,
    const __half* __restrict__ Bt,
    const float* __restrict__ bias,
    float* __restrict__ C, int ldc, int K, int ntiles, int mtiles)
{
    extern __shared__ char smc[];

    int lin = blockIdx.x;
    int n_t, m_t;
    {
        int full = ntiles / GSW;
        int blocksFull = full * GSW * mtiles;
        if (lin < blocksFull) {
            int sid = lin / (GSW * mtiles);
            int r = lin - sid * (GSW * mtiles);
            n_t = sid * GSW + (r % GSW);
            m_t = r / GSW;
        } else {
            int r = lin - blocksFull;
            int wd = ntiles - full * GSW;
            n_t = full * GSW + (r % wd);
            m_t = r / wd;
        }
    }
    const int n0 = n_t * GBN;
    const int m0 = m_t * GBM;

    const int tid = threadIdx.x;
    const int lane = tid & 31, warp = tid >> 5;
    const int wm = (warp & 1) * 64;
    const int wn = (warp >> 1) * 64;
    const int g = lane >> 2, tig = lane & 3;

    const uint32_t sm_u32 = (uint32_t)__cvta_generic_to_shared(smc);

    float acc[4][8][4];
#pragma unroll
    for (int i = 0; i < 4; i++)
#pragma unroll
        for (int j = 0; j < 8; j++)
#pragma unroll
            for (int r = 0; r < 4; r++) acc[i][j][r] = 0.f;

    auto issue_stage = [&](int kb, int s) {
        int k0 = kb * GBK;
        uint32_t aS = sm_u32 + (uint32_t)(s * STAGE_H) * 2;
        uint32_t bS = aS + A_STAGE_H * 2;
#pragma unroll
        for (int i = 0; i < 4; i++) {
            int idx = tid + i * 256;
            int row = idx >> 3, kq = (idx & 7) << 3;
            cp16(aS + (uint32_t)(row * ASTH + kq) * 2,
                 A + (size_t)(m0 + row) * lda + k0 + kq);
        }
#pragma unroll
        for (int i = 0; i < 8; i++) {
            int idx = tid + i * 256;
            int row = idx >> 3, kq = (idx & 7) << 3;
            cp16(bS + (uint32_t)(row * BSTH + kq) * 2,
                 Bt + (size_t)(n0 + row) * K + k0 + kq);
        }
        CP_COMMIT();
    };
    auto compute_stage = [&](int s) {
        const __half* aS = reinterpret_cast<const __half*>(smc) + s * STAGE_H;
        const __half* bS = aS + A_STAGE_H;
#pragma unroll
        for (int it = 0; it < 4; it++) {
            const int ks = it * 16;
            uint32_t af[4][4];
#pragma unroll
            for (int mt = 0; mt < 4; mt++) {
                int mb = wm + mt * 16 + g;
                af[mt][0] = *reinterpret_cast<const uint32_t*>(aS + mb * ASTH + ks + 2 * tig);
                af[mt][1] = *reinterpret_cast<const uint32_t*>(aS + (mb + 8) * ASTH + ks + 2 * tig);
                af[mt][2] = *reinterpret_cast<const uint32_t*>(aS + mb * ASTH + ks + 2 * tig + 8);
                af[mt][3] = *reinterpret_cast<const uint32_t*>(aS + (mb + 8) * ASTH + ks + 2 * tig + 8);
            }
#pragma unroll
            for (int nt = 0; nt < 8; nt++) {
                int nb = wn + nt * 8 + g;
                uint32_t bf[2];
                bf[0] = *reinterpret_cast<const uint32_t*>(bS + nb * BSTH + ks + 2 * tig);
                bf[1] = *reinterpret_cast<const uint32_t*>(bS + nb * BSTH + ks + 2 * tig + 8);
#pragma unroll
                for (int mt = 0; mt < 4; mt++)
                    mma_fp16(acc[mt][nt], af[mt], bf);
            }
        }
    };

    const int nk = K >> 6;
    issue_stage(0, 0);
    issue_stage(1, 1);
    int s = 0;
    for (int kb = 0; kb < nk; kb++) {
        if (kb < nk - 1) { CP_WAIT(1); } else { CP_WAIT(0); }
        __syncthreads();
        compute_stage(s);
        if (kb + 2 < nk) {
            int nb = s + 2; if (nb >= 3) nb -= 3;
            issue_stage(kb + 2, nb);
        }
        s = s + 1; if (s == 3) s = 0;
    }

#pragma unroll
    for (int mt = 0; mt < 4; mt++) {
        int m = m0 + wm + mt * 16 + g;
#pragma unroll
        for (int nt = 0; nt < 8; nt++) {
            int n = n0 + wn + nt * 8 + 2 * tig;
            float bx = bias[n], by = bias[n + 1];
            float2 v0 = make_float2(acc[mt][nt][0] + bx, acc[mt][nt][1] + by);
            float2 v1 = make_float2(acc[mt][nt][2] + bx, acc[mt][nt][3] + by);
            *reinterpret_cast<float2*>(C + (size_t)m * ldc + n) = v0;
            *reinterpret_cast<float2*>(C + (size_t)(m + 8) * ldc + n) = v1;
        }
    }
}

// ---------------- persistent LSTM layer: fp16 mma, distributed barrier ------
#define WHS_BYTES 65536
#define HB_BYTES  (NW * 2 * CBH)       // 40960
#define SMEM_PERSIST (WHS_BYTES + HB_BYTES)

__global__ __launch_bounds__(256, 1) void lstm_persist(
    const float* __restrict__ Xg,
    const float* __restrict__ Wh,      // f32 [HID_][G_] (rows Din..Din+H of W)
    __half* __restrict__ hbuf,         // half [2][BH] (zeroed)
    __half* __restrict__ Hout,         // half for next layer's fp16 GEMM
    unsigned* __restrict__ bar)        // [NCTR*32] distributed counters
{
    extern __shared__ char smx[];
    uint2* Whs = reinterpret_cast<uint2*>(smx);          // [64 ko][4 nt][32 lane]
    float* scr = reinterpret_cast<float*>(smx + WHS_BYTES);  // alias of chunk bufs

    const int tid = threadIdx.x;
    const int lane = tid & 31, warp = tid >> 5;
    const int g = lane >> 2, tig = lane & 3;
    const int u0 = blockIdx.x * UPB;

    const uint32_t smem_u32 = (uint32_t)__cvta_generic_to_shared(smx);
    const uint32_t hb_u32 = smem_u32 + WHS_BYTES + warp * 2 * CBH;
    const uint32_t* hb_gen =
        reinterpret_cast<const uint32_t*>(smx + WHS_BYTES + warp * 2 * CBH);

    // ---- one-time: Wh slice -> half B-fragments (m16n8k16) ----
    for (int ko = warp; ko < 64; ko += NW) {
        int k0 = ko * 16;
#pragma unroll
        for (int nt = 0; nt < 4; nt++) {
            int col = nt * HID_ + u0 + g;
            uint32_t r0 = pack_half2(Wh[(size_t)(k0 + 2 * tig) * G_ + col],
                                     Wh[(size_t)(k0 + 2 * tig + 1) * G_ + col]);
            uint32_t r1 = pack_half2(Wh[(size_t)(k0 + 2 * tig + 8) * G_ + col],
                                     Wh[(size_t)(k0 + 2 * tig + 9) * G_ + col]);
            Whs[(ko * 4 + nt) * 32 + lane] = make_uint2(r0, r1);
        }
    }
    __syncthreads();

    // pointwise mapping (identical output layout to previous rounds)
    const int pm = tid >> 3, pul = tid & 7;
    const int pmt = pm >> 4;
    const int pgg = (pm & 15) & 7, phi = (pm & 15) >> 3;
    const int pr = phi * 2 + (pul & 1);
    const int pln = pgg * 4 + (pul >> 1);
    const size_t xgbase = (size_t)pm * G_ + u0 + pul;

    const int kw = warp * 128;         // this warp's K base (halves)

    float creg = 0.f;
    float xr[4];
#pragma unroll
    for (int s = 0; s < 4; s++) xr[s] = Xg[xgbase + s * HID_];

    for (int t = 0; t < T_; t++) {
        const __half* hin = hbuf + (t & 1) * BH;
        __half* hnx = hbuf + ((t + 1) & 1) * BH;

        float acc[2][4][4];
#pragma unroll
        for (int mt = 0; mt < 2; mt++)
#pragma unroll
            for (int nt = 0; nt < 4; nt++)
#pragma unroll
                for (int r = 0; r < 4; r++) acc[mt][nt][r] = 0.f;

        // chunk = 32 m x 32 k halves; 128 cp16 per chunk, 4 per lane
        auto cp_chunk = [&](int c, int b) {
            const int kbase = kw + c * 32;
            const uint32_t dbase = hb_u32 + b * CBH;
#pragma unroll
            for (int i = 0; i < 4; i++) {
                int idx = i * 32 + lane;
                int row = idx >> 2, q = idx & 3;
                cp16(dbase + (uint32_t)(row * (CSTH * 2) + q * 16),
                     hin + (size_t)row * HID_ + kbase + q * 8);
            }
            CP_COMMIT();
        };
        auto compute_chunk = [&](int c, int b) {
            const uint32_t* buf = hb_gen + b * (CBH / 4);
#pragma unroll
            for (int ks16 = 0; ks16 < 2; ks16++) {
                int ko = warp * 8 + c * 2 + ks16;
                uint32_t af[2][4];
#pragma unroll
                for (int mt = 0; mt < 2; mt++) {
                    int mb = mt * 16;
                    int base0 = (mb + g) * (CSTH / 2) + ks16 * 8 + tig;
                    int base1 = (mb + g + 8) * (CSTH / 2) + ks16 * 8 + tig;
                    af[mt][0] = buf[base0];
                    af[mt][1] = buf[base1];
                    af[mt][2] = buf[base0 + 4];
                    af[mt][3] = buf[base1 + 4];
                }
#pragma unroll
                for (int nt = 0; nt < 4; nt++) {
                    uint2 bb = Whs[(ko * 4 + nt) * 32 + lane];
                    uint32_t bf[2] = {bb.x, bb.y};
                    mma_fp16(acc[0][nt], af[0], bf);
                    mma_fp16(acc[1][nt], af[1], bf);
                }
            }
        };

        cp_chunk(0, 0);
        cp_chunk(1, 1);
        CP_WAIT(1); __syncwarp();
        compute_chunk(0, 0);
        cp_chunk(2, 0);
        CP_WAIT(1); __syncwarp();
        compute_chunk(1, 1);
        cp_chunk(3, 1);
        CP_WAIT(1); __syncwarp();
        compute_chunk(2, 0);
        CP_WAIT(0); __syncwarp();
        compute_chunk(3, 1);

        // ---- reduce K-partials across 8 warps (scr aliases chunk bufs) ----
        __syncthreads();
#pragma unroll
        for (int mt = 0; mt < 2; mt++)
#pragma unroll
            for (int nt = 0; nt < 4; nt++)
#pragma unroll
                for (int r = 0; r < 4; r++) {
                    int ridx = mt * 16 + nt * 4 + r;
                    scr[((warp * 32 + ridx) << 5) + lane] = acc[mt][nt][r];
                }
        __syncthreads();

        // ---- pointwise: one (batch, unit) pair per thread ----
        float hh;
        {
            float gv[4];
#pragma unroll
            for (int s = 0; s < 4; s++) {
                int ridx = pmt * 16 + s * 4 + pr;
                float v = 0.f;
#pragma unroll
                for (int w = 0; w < NW; w++)
                    v += scr[((w * 32 + ridx) << 5) + pln];
                gv[s] = v + xr[s];
            }
            float cc = creg;
            cc = sigm(gv[2] + 1.f) * cc + sigm(gv[0]) * tanhf(gv[1]);
            hh = sigm(gv[3]) * tanhf(cc);
            creg = cc;
            hnx[pm * HID_ + u0 + pul] = __float2half(hh);
        }

        // ---- distributed barrier: 8 counters x 16 arrivals ----
        if (t < T_ - 1) {
            __syncthreads();           // all hnx stores issued
            if (tid == 0) {
                __threadfence();
                atomicAdd(&bar[(blockIdx.x & (NCTR - 1)) << 5], 1u);
            }
            // overlap latency of arrival propagation
            Hout[((size_t)(t * B_ + pm)) * HID_ + u0 + pul] = __float2half(hh);
            const size_t xb = xgbase + (size_t)(t + 1) * B_ * G_;
#pragma unroll
            for (int s = 0; s < 4; s++) xr[s] = Xg[xb + s * HID_];
            if (warp == 0 && lane < NCTR) {
                const unsigned target = (unsigned)(t + 1) * (NBLK / NCTR);
                while (ld_acq(&bar[lane << 5]) < target) { }
            }
            __syncthreads();
        } else {
            Hout[((size_t)(t * B_ + pm)) * HID_ + u0 + pul] = __float2half(hh);
        }
    }
}

// ---------------- launch ----------------------------------------------------
extern "C" void kernel_launch(void* const* d_in, const int* in_sizes, int n_in,
                              void* d_out, int out_size) {
    const int*   data = (const int*)d_in[0];
    const float* emb  = (const float*)d_in[2];
    const float* W0   = (const float*)d_in[3];
    const float* b0   = (const float*)d_in[4];
    const float* W1   = (const float*)d_in[5];
    const float* b1   = (const float*)d_in[6];
    const float* W2   = (const float*)d_in[7];
    const float* b2   = (const float*)d_in[8];
    const float* Wd   = (const float*)d_in[9];
    const float* bd   = (const float*)d_in[10];
    float* out = (float*)d_out;
    (void)in_sizes; (void)n_in; (void)out_size;

    float *X0, *HA, *HB, *Xg, *Wr, *h;
    unsigned* bar;
    cudaGetSymbolAddress((void**)&X0, g_X0);
    cudaGetSymbolAddress((void**)&HA, g_HA);
    cudaGetSymbolAddress((void**)&HB, g_HB);
    cudaGetSymbolAddress((void**)&Xg, g_Xg);
    cudaGetSymbolAddress((void**)&Wr, g_Wr);
    cudaGetSymbolAddress((void**)&h,  g_h);
    cudaGetSymbolAddress((void**)&bar, g_bar);

    __half* X0h = reinterpret_cast<__half*>(X0);
    __half* HAh = reinterpret_cast<__half*>(HA);
    __half* HBh = reinterpret_cast<__half*>(HB);
    __half* Wrh = reinterpret_cast<__half*>(Wr);
    __half* WdTh = reinterpret_cast<__half*>(Xg);
    __half* hh_ = reinterpret_cast<__half*>(h);

    cudaFuncSetAttribute(lstm_persist, cudaFuncAttributeMaxDynamicSharedMemorySize,
                         SMEM_PERSIST);
    cudaFuncSetAttribute(gemm_fp16_pipe, cudaFuncAttributeMaxDynamicSharedMemorySize,
                         GEMM_SMEM);

    gather_kernel<<<TB_, 128>>>(data, emb, X0h);

    const int zgrid = (2 * BH + 255) / 256;
    const int MT = TB_ / GBM;          // 64

    // layer 0 (Din = 512)
    trans_half<<<dim3(G_ / 32, EMB_ / 32), dim3(32, 8)>>>(W0, Wrh, EMB_, G_);
    zero_state<<<zgrid, 256>>>(h, bar);
    gemm_fp16_pipe<<<MT * (G_ / GBN), 256, GEMM_SMEM>>>(
        X0h, EMB_, Wrh, b0, Xg, G_, EMB_, G_ / GBN, MT);
    lstm_persist<<<NBLK, 256, SMEM_PERSIST>>>(Xg, W0 + (size_t)EMB_ * G_, hh_, HAh, bar);

    // layer 1
    trans_half<<<dim3(G_ / 32, HID_ / 32), dim3(32, 8)>>>(W1, Wrh, HID_, G_);
    zero_state<<<zgrid, 256>>>(h, bar);
    gemm_fp16_pipe<<<MT * (G_ / GBN), 256, GEMM_SMEM>>>(
        HAh, HID_, Wrh, b1, Xg, G_, HID_, G_ / GBN, MT);
    lstm_persist<<<NBLK, 256, SMEM_PERSIST>>>(Xg, W1 + (size_t)HID_ * G_, hh_, HBh, bar);

    // layer 2
    trans_half<<<dim3(G_ / 32, HID_ / 32), dim3(32, 8)>>>(W2, Wrh, HID_, G_);
    zero_state<<<zgrid, 256>>>(h, bar);
    gemm_fp16_pipe<<<MT * (G_ / GBN), 256, GEMM_SMEM>>>(
        HBh, HID_, Wrh, b2, Xg, G_, HID_, G_ / GBN, MT);
    lstm_persist<<<NBLK, 256, SMEM_PERSIST>>>(Xg, W2 + (size_t)HID_ * G_, hh_, HAh, bar);

    // projection: Wd^T (half) into the now-dead Xg buffer, then fp16 GEMM
    trans_half<<<dim3(VOCAB_ / 32, HID_ / 32), dim3(32, 8)>>>(Wd, WdTh, HID_, VOCAB_);
    gemm_fp16_pipe<<<MT * (VOCAB_ / GBN), 256, GEMM_SMEM>>>(
        HAh, HID_, WdTh, bd, out, VOCAB_, HID_, VOCAB_ / GBN, MT);
}